// round 6
// baseline (speedup 1.0000x reference)
#include <cuda_runtime.h>
#include <cstdint>
#include <math.h>

// Shapes (fixed): B=32, T=2000, D=512, halves of 256, 3H=768.
#define M_TOTAL   64000
#define B_SZ      32
#define T_LEN     2000
#define D_FULL    512
#define D_HALF    256
#define N_COLS    768

// Scan chunking
#define NCHUNK 40
#define CLEN   50

// GEMM tiling (mma.sync tf32)
#define BM 128
#define BN 128
#define BK 16
#define NKT (D_HALF / BK)        // 16 k-tiles

// Scratch (device globals: allocation-free per harness rules).
__device__ float g_xt[M_TOTAL * D_FULL];
__device__ float g_f [M_TOTAL * D_FULL];
__device__ float g_r [M_TOTAL * D_FULL];
__device__ float g_P  [B_SZ * NCHUNK * D_FULL];
__device__ float g_C  [B_SZ * NCHUNK * D_FULL];
__device__ float g_cin[B_SZ * NCHUNK * D_FULL];

__device__ __forceinline__ float sigmoidf_(float v) {
    return 1.0f / (1.0f + __expf(-v));
}

__device__ __forceinline__ uint32_t to_tf32(float v) {
    uint32_t d;
    asm("cvt.rna.tf32.f32 %0, %1;" : "=r"(d) : "f"(v));
    return d;
}

__device__ __forceinline__ void mma_tf32(float* c, const uint32_t* a, const uint32_t* b) {
    asm volatile(
        "mma.sync.aligned.m16n8k8.row.col.f32.tf32.tf32.f32 "
        "{%0,%1,%2,%3}, {%4,%5,%6,%7}, {%8,%9}, {%0,%1,%2,%3};"
        : "+f"(c[0]), "+f"(c[1]), "+f"(c[2]), "+f"(c[3])
        : "r"(a[0]), "r"(a[1]), "r"(a[2]), "r"(a[3]), "r"(b[0]), "r"(b[1]));
}

// ---------------------------------------------------------------------------
// Kernel 1: tf32 mma.sync GEMM, 128x128 block, BK=16.
// SMEM holds pre-converted tf32 bits in a k-permuted + XOR-swizzled layout:
//   element (row, k) lives at row*16 + 4*((k&3)^(row&3)^((row>>2)&1)) + (k>>2)
// so a thread's full k-fragment set {tig, tig+4, tig+8, tig+12} is ONE LDS.128.
// Register-staged double buffer (ldg next / compute cur / store next / sync).
// 8 warps = 2(m) x 4(n); warp tile 64x32 = 4x4 frags of m16n8k8.
// Grid: (12, 500) — x encodes (half, nblk); y = mblk. 256 threads.
// ---------------------------------------------------------------------------
__global__ __launch_bounds__(256, 2)
void gemm_mma_kernel(const float* __restrict__ x,
                     const float* __restrict__ W1, const float* __restrict__ bf1,
                     const float* __restrict__ br1,
                     const float* __restrict__ W2, const float* __restrict__ bf2,
                     const float* __restrict__ br2)
{
    const int s    = blockIdx.x / 6;     // half 0/1
    const int nblk = blockIdx.x % 6;     // 0..5
    const int mblk = blockIdx.y;         // 0..499

    const float* W  = s ? W2  : W1;
    const float* bf = s ? bf2 : bf1;
    const float* br = s ? br2 : br1;

    __shared__ uint32_t sA[2][BM * BK];  // 2 x 8KB (tf32 bits)
    __shared__ uint32_t sB[2][BN * BK];  // 2 x 8KB

    const int tid    = threadIdx.x;
    const int wid    = tid >> 5;
    const int lid    = tid & 31;
    const int gid    = lid >> 2;         // 0..7
    const int tig    = lid & 3;          // 0..3
    const int warp_m = wid >> 2;         // 0..1
    const int warp_n = wid & 3;          // 0..3

    const float* Agbl = x + (size_t)(mblk * BM) * D_FULL + s * D_HALF;
    const float* Bgbl = W + nblk * BN;

    // gmem staging maps
    const int a_row = tid >> 2;          // 0..63 (+64 for jj=1)
    const int a_c   = tid & 3;           // float4 chunk along k
    const int b_k   = tid & 15;          // k within tile
    const int b_n4  = tid >> 4;          // 0..15 (+16 for jj=1), float4 chunk along n

    float4 stA[2], stB[2];

    float acc[4][4][4];
    #pragma unroll
    for (int mi = 0; mi < 4; mi++)
        #pragma unroll
        for (int ni = 0; ni < 4; ni++)
            #pragma unroll
            for (int q = 0; q < 4; q++) acc[mi][ni][q] = 0.0f;

    // fragment-read swizzle (independent of mi/ni/h — proven by bit analysis)
    const int fr_swz = (gid & 3) ^ ((gid >> 2) & 1);
    const int fr_grp = tig ^ fr_swz;

    // ---- pipeline helpers ----
    auto ldg_tile = [&](int kt) {
        stA[0] = *(const float4*)(Agbl + (size_t)a_row * D_FULL + kt * BK + 4 * a_c);
        stA[1] = *(const float4*)(Agbl + (size_t)(a_row + 64) * D_FULL + kt * BK + 4 * a_c);
        stB[0] = *(const float4*)(Bgbl + (size_t)(kt * BK + b_k) * N_COLS + 4 * b_n4);
        stB[1] = *(const float4*)(Bgbl + (size_t)(kt * BK + b_k) * N_COLS + 4 * (b_n4 + 16));
    };

    auto st_tile = [&](int buf) {
        #pragma unroll
        for (int jj = 0; jj < 2; jj++) {
            const int row = a_row + 64 * jj;
            const int swz = (row & 3) ^ ((row >> 2) & 1);
            const float v[4] = {stA[jj].x, stA[jj].y, stA[jj].z, stA[jj].w};
            #pragma unroll
            for (int i = 0; i < 4; i++)
                sA[buf][row * 16 + 4 * (i ^ swz) + a_c] = to_tf32(v[i]);
        }
        #pragma unroll
        for (int jj = 0; jj < 2; jj++) {
            const int n4 = b_n4 + 16 * jj;
            const float v[4] = {stB[jj].x, stB[jj].y, stB[jj].z, stB[jj].w};
            #pragma unroll
            for (int i = 0; i < 4; i++) {
                const int n = 4 * n4 + i;
                sB[buf][n * 16 + 4 * ((b_k & 3) ^ (n & 3) ^ ((n >> 2) & 1)) + (b_k >> 2)]
                    = to_tf32(v[i]);
            }
        }
    };

    // ---- prologue ----
    ldg_tile(0);
    st_tile(0);
    __syncthreads();

    #pragma unroll 1
    for (int kt = 0; kt < NKT; kt++) {
        if (kt + 1 < NKT) ldg_tile(kt + 1);

        const uint32_t* A  = sA[kt & 1];
        const uint32_t* Bs = sB[kt & 1];

        uint4 afr[4][2];
        #pragma unroll
        for (int mi = 0; mi < 4; mi++)
            #pragma unroll
            for (int h = 0; h < 2; h++) {
                const int m = warp_m * 64 + mi * 16 + gid + 8 * h;
                afr[mi][h] = *(const uint4*)&A[m * 16 + 4 * fr_grp];
            }

        #pragma unroll
        for (int ni = 0; ni < 4; ni++) {
            const int n = warp_n * 32 + ni * 8 + gid;
            const uint4 bv = *(const uint4*)&Bs[n * 16 + 4 * fr_grp];
            #pragma unroll
            for (int mi = 0; mi < 4; mi++) {
                const uint32_t a0[4] = {afr[mi][0].x, afr[mi][1].x,
                                        afr[mi][0].y, afr[mi][1].y};
                const uint32_t b0[2] = {bv.x, bv.y};
                mma_tf32(acc[mi][ni], a0, b0);
                const uint32_t a1[4] = {afr[mi][0].z, afr[mi][1].z,
                                        afr[mi][0].w, afr[mi][1].w};
                const uint32_t b1[2] = {bv.z, bv.w};
                mma_tf32(acc[mi][ni], a1, b1);
            }
        }

        if (kt + 1 < NKT) {
            st_tile((kt + 1) & 1);
            __syncthreads();
        }
    }

    // ---- epilogue: fused bias + sigmoid, float2 stores ----
    const int n0      = nblk * BN;           // 0..640
    const int region  = n0 >> 8;             // 0=xt, 1=f, 2=r
    float* dst        = (region == 0) ? g_xt : ((region == 1) ? g_f : g_r);
    const float* bias = (region == 1) ? bf : br;

    #pragma unroll
    for (int mi = 0; mi < 4; mi++) {
        const int row0 = mblk * BM + warp_m * 64 + mi * 16 + gid;
        #pragma unroll
        for (int ni = 0; ni < 4; ni++) {
            const int h = (n0 & (D_HALF - 1)) + warp_n * 32 + ni * 8 + 2 * tig;
            float v0 = acc[mi][ni][0], v1 = acc[mi][ni][1];
            float v2 = acc[mi][ni][2], v3 = acc[mi][ni][3];
            if (region != 0) {
                const float b0 = __ldg(bias + h), b1 = __ldg(bias + h + 1);
                v0 = sigmoidf_(v0 + b0);
                v1 = sigmoidf_(v1 + b1);
                v2 = sigmoidf_(v2 + b0);
                v3 = sigmoidf_(v3 + b1);
            }
            const size_t col = (size_t)s * D_HALF + h;
            *(float2*)(dst + (size_t)row0 * D_FULL + col)       = make_float2(v0, v1);
            *(float2*)(dst + (size_t)(row0 + 8) * D_FULL + col) = make_float2(v2, v3);
        }
    }
}

// ---------------------------------------------------------------------------
// Scan phase 1: per (b, chunk, c) local affine summary (P, C).
// ---------------------------------------------------------------------------
__global__ __launch_bounds__(256)
void scan_phase1(void)
{
    const int c     = blockIdx.x * 256 + threadIdx.x;
    const int chunk = blockIdx.y;
    const int b     = blockIdx.z;

    const size_t base = ((size_t)b * T_LEN + (size_t)chunk * CLEN) * D_FULL + c;
    const float* pf  = g_f  + base;
    const float* pxt = g_xt + base;

    float P = 1.0f, C = 0.0f;
    #pragma unroll 5
    for (int t = 0; t < CLEN; t++) {
        const size_t off = (size_t)t * D_FULL;
        const float f  = pf [off];
        const float xt = pxt[off];
        C = fmaf(f, C, (1.0f - f) * xt);
        P *= f;
    }
    const size_t sidx = ((size_t)b * NCHUNK + chunk) * D_FULL + c;
    g_P[sidx] = P;
    g_C[sidx] = C;
}

// ---------------------------------------------------------------------------
// Scan phase 2: serial scan over chunk summaries -> carry-in per chunk.
// ---------------------------------------------------------------------------
__global__ __launch_bounds__(256)
void scan_phase2(void)
{
    const int idx = blockIdx.x * 256 + threadIdx.x;
    const int b = idx >> 9;
    const int c = idx & (D_FULL - 1);

    float carry = 0.0f;
    #pragma unroll
    for (int k = 0; k < NCHUNK; k++) {
        const size_t sidx = ((size_t)b * NCHUNK + k) * D_FULL + c;
        g_cin[sidx] = carry;
        carry = fmaf(g_P[sidx], carry, g_C[sidx]);
    }
}

// ---------------------------------------------------------------------------
// Scan phase 3: recurrence from carry-in; fused highway output.
// ---------------------------------------------------------------------------
__global__ __launch_bounds__(256)
void scan_phase3(const float* __restrict__ x, float* __restrict__ out)
{
    const int c     = blockIdx.x * 256 + threadIdx.x;
    const int chunk = blockIdx.y;
    const int b     = blockIdx.z;

    const size_t base = ((size_t)b * T_LEN + (size_t)chunk * CLEN) * D_FULL + c;
    const float* pf  = g_f  + base;
    const float* pxt = g_xt + base;
    const float* pr  = g_r  + base;
    const float* px  = x    + base;
    float*       po  = out  + base;

    float cacc = g_cin[((size_t)b * NCHUNK + chunk) * D_FULL + c];

    #pragma unroll 5
    for (int t = 0; t < CLEN; t++) {
        const size_t off = (size_t)t * D_FULL;
        const float f  = pf [off];
        const float xt = pxt[off];
        const float r  = pr [off];
        const float xv = px [off];
        cacc = fmaf(f, cacc, (1.0f - f) * xt);
        po[off] = fmaf(r, cacc, (1.0f - r) * xv);
    }
}

// ---------------------------------------------------------------------------
extern "C" void kernel_launch(void* const* d_in, const int* in_sizes, int n_in,
                              void* d_out, int out_size)
{
    const float* x   = (const float*)d_in[0];
    const float* W1  = (const float*)d_in[1];
    const float* bf1 = (const float*)d_in[2];
    const float* br1 = (const float*)d_in[3];
    const float* W2  = (const float*)d_in[4];
    const float* bf2 = (const float*)d_in[5];
    const float* br2 = (const float*)d_in[6];
    float* out = (float*)d_out;

    (void)n_in; (void)in_sizes; (void)out_size;

    dim3 ggrid(12, M_TOTAL / BM);              // (12, 500)
    gemm_mma_kernel<<<ggrid, 256>>>(x, W1, bf1, br1, W2, bf2, br2);

    dim3 sgrid(2, NCHUNK, B_SZ);               // (2, 40, 32)
    scan_phase1<<<sgrid, 256>>>();
    scan_phase2<<<(B_SZ * D_FULL) / 256, 256>>>();
    scan_phase3<<<sgrid, 256>>>(x, out);
}

// round 8
// speedup vs baseline: 1.2461x; 1.2461x over previous
#include <cuda_runtime.h>
#include <cstdint>
#include <math.h>

// Shapes (fixed): B=32, T=2000, D=512, halves of 256, 3H=768.
#define M_TOTAL   64000
#define B_SZ      32
#define T_LEN     2000
#define D_FULL    512
#define D_HALF    256
#define N_COLS    768

// Scan chunking
#define NCHUNK 40
#define CLEN   50

// GEMM tiling (mma.sync tf32)
#define BM 128
#define BN 128
#define BK 16
#define NKT (D_HALF / BK)        // 16 k-tiles
#define NMBLK (M_TOTAL / BM)     // 500
#define TILE_ELEMS (BM * BK)     // 2048 elements = 8KB

// Scratch (device globals: allocation-free per harness rules).
__device__ float g_xt[M_TOTAL * D_FULL];
__device__ float g_f [M_TOTAL * D_FULL];
__device__ float g_r [M_TOTAL * D_FULL];
__device__ float g_P  [B_SZ * NCHUNK * D_FULL];
__device__ float g_C  [B_SZ * NCHUNK * D_FULL];
__device__ float g_cin[B_SZ * NCHUNK * D_FULL];
// pre-converted, pre-permuted operand images (tf32 bits, SMEM tile layout)
__device__ uint32_t g_xc[2 * NMBLK * NKT * TILE_ELEMS];   // 131 MB
__device__ uint32_t g_wc[2 * 6 * NKT * TILE_ELEMS];       // 1.5 MB

__device__ __forceinline__ float sigmoidf_(float v) {
    return 1.0f / (1.0f + __expf(-v));
}

__device__ __forceinline__ uint32_t smem_u32(const void* p) {
    uint32_t a;
    asm("{ .reg .u64 t; cvta.to.shared.u64 t, %1; cvt.u32.u64 %0, t; }"
        : "=r"(a) : "l"(p));
    return a;
}

__device__ __forceinline__ uint32_t to_tf32(float v) {
    uint32_t d;
    asm("cvt.rna.tf32.f32 %0, %1;" : "=r"(d) : "f"(v));
    return d;
}

__device__ __forceinline__ void cp_async16(uint32_t smem_dst, const void* gptr) {
    asm volatile("cp.async.ca.shared.global [%0], [%1], 16;"
                 :: "r"(smem_dst), "l"(gptr) : "memory");
}
__device__ __forceinline__ void cp_async_commit() {
    asm volatile("cp.async.commit_group;" ::: "memory");
}
template <int N>
__device__ __forceinline__ void cp_async_wait() {
    asm volatile("cp.async.wait_group %0;" :: "n"(N) : "memory");
}

__device__ __forceinline__ void mma_tf32(float* c, const uint32_t* a, const uint32_t* b) {
    asm volatile(
        "mma.sync.aligned.m16n8k8.row.col.f32.tf32.tf32.f32 "
        "{%0,%1,%2,%3}, {%4,%5,%6,%7}, {%8,%9}, {%0,%1,%2,%3};"
        : "+f"(c[0]), "+f"(c[1]), "+f"(c[2]), "+f"(c[3])
        : "r"(a[0]), "r"(a[1]), "r"(a[2]), "r"(a[3]), "r"(b[0]), "r"(b[1]));
}

// Permuted in-tile index: element (row, k) -> row*16 + 4*((k&3)^(row&3)^((row>>2)&1)) + (k>>2)
__device__ __forceinline__ int perm_idx(int row, int k) {
    return row * 16 + 4 * ((k & 3) ^ (row & 3) ^ ((row >> 2) & 1)) + (k >> 2);
}

// ---------------------------------------------------------------------------
// Pre-pass A: x -> g_xc (tf32 bits, tile-major [s][mblk][kt], permuted tiles).
// ---------------------------------------------------------------------------
__global__ __launch_bounds__(256)
void convert_x_kernel(const float* __restrict__ x)
{
    const int kt   = blockIdx.x;     // 0..15
    const int mblk = blockIdx.y;     // 0..499
    const int s    = blockIdx.z;     // 0..1

    const int tid = threadIdx.x;
    uint32_t* dst = g_xc + ((size_t)((s * NMBLK + mblk) * NKT + kt)) * TILE_ELEMS;
    const float* src = x + (size_t)(mblk * BM) * D_FULL + s * D_HALF + kt * BK;

    #pragma unroll
    for (int j = 0; j < 2; j++) {
        const int idx = tid + 256 * j;        // 0..511
        const int row = idx >> 2;             // 0..127
        const int c4  = idx & 3;              // float4 along k
        float4 v = *(const float4*)(src + (size_t)row * D_FULL + 4 * c4);
        const float vv[4] = {v.x, v.y, v.z, v.w};
        #pragma unroll
        for (int i = 0; i < 4; i++)
            dst[perm_idx(row, 4 * c4 + i)] = to_tf32(vv[i]);
    }
}

// ---------------------------------------------------------------------------
// Pre-pass B: W1/W2 -> g_wc (tf32 bits, tile-major [s][nblk][kt], permuted,
// transposed to [n][k]).
// ---------------------------------------------------------------------------
__global__ __launch_bounds__(256)
void convert_w_kernel(const float* __restrict__ W1, const float* __restrict__ W2)
{
    const int kt   = blockIdx.x;     // 0..15
    const int nblk = blockIdx.y;     // 0..5
    const int s    = blockIdx.z;     // 0..1

    const int tid = threadIdx.x;
    const float* W = s ? W2 : W1;
    uint32_t* dst = g_wc + ((size_t)((s * 6 + nblk) * NKT + kt)) * TILE_ELEMS;
    const float* src = W + (size_t)(kt * BK) * N_COLS + nblk * BN;

    #pragma unroll
    for (int j = 0; j < 8; j++) {
        const int idx = tid + 256 * j;        // 0..2047 = k*128 + n
        const int k = idx >> 7;
        const int n = idx & 127;
        dst[perm_idx(n, k)] = to_tf32(src[(size_t)k * N_COLS + n]);
    }
}

// ---------------------------------------------------------------------------
// Kernel 1: tf32 mma.sync GEMM from pre-permuted images.
// cp.async 3-stage pipeline; 12 LDS.128 + 32 MMA per thread per k-tile.
// ---------------------------------------------------------------------------
__global__ __launch_bounds__(256, 2)
void gemm_mma_kernel(const float* __restrict__ bf1, const float* __restrict__ br1,
                     const float* __restrict__ bf2, const float* __restrict__ br2)
{
    const int s    = blockIdx.x / 6;     // half 0/1
    const int nblk = blockIdx.x % 6;     // 0..5
    const int mblk = blockIdx.y;         // 0..499

    const float* bf = s ? bf2 : bf1;
    const float* br = s ? br2 : br1;

    __shared__ uint32_t sA[3][TILE_ELEMS];  // 3 x 8KB
    __shared__ uint32_t sB[3][TILE_ELEMS];  // 3 x 8KB

    const int tid    = threadIdx.x;
    const int wid    = tid >> 5;
    const int lid    = tid & 31;
    const int gid    = lid >> 2;         // 0..7
    const int tig    = lid & 3;          // 0..3
    const int warp_m = wid >> 2;         // 0..1
    const int warp_n = wid & 3;          // 0..3

    const uint32_t* Asrc = g_xc + ((size_t)(s * NMBLK + mblk)) * NKT * TILE_ELEMS;
    const uint32_t* Bsrc = g_wc + ((size_t)(s * 6 + nblk)) * NKT * TILE_ELEMS;

    auto prefetch = [&](int kt) {
        const int buf = kt % 3;
        const uint32_t* ga = Asrc + (size_t)kt * TILE_ELEMS;
        const uint32_t* gb = Bsrc + (size_t)kt * TILE_ELEMS;
        #pragma unroll
        for (int j = 0; j < 2; j++) {
            const int e = (tid + 256 * j) * 4;      // element offset (uint4)
            cp_async16(smem_u32(&sA[buf][e]), ga + e);
            cp_async16(smem_u32(&sB[buf][e]), gb + e);
        }
        cp_async_commit();
    };

    float acc[4][4][4];
    #pragma unroll
    for (int mi = 0; mi < 4; mi++)
        #pragma unroll
        for (int ni = 0; ni < 4; ni++)
            #pragma unroll
            for (int q = 0; q < 4; q++) acc[mi][ni][q] = 0.0f;

    // fragment group select (validated in R5): grp = tig ^ (gid&3) ^ ((gid>>2)&1)
    const int fr_off = 4 * (tig ^ (gid & 3) ^ ((gid >> 2) & 1));

    prefetch(0);
    prefetch(1);

    #pragma unroll 1
    for (int kt = 0; kt < NKT; kt++) {
        // TAIL FIX (R6 bug): at the last iter the final group (NKT-1) is the
        // newest committed group; wait_group 1 would leave it in flight while
        // we read its tile. Drain fully there.
        if (kt + 1 < NKT) cp_async_wait<1>();
        else              cp_async_wait<0>();
        __syncthreads();                    // tile kt resident; compute kt-1 done everywhere
        if (kt + 2 < NKT) prefetch(kt + 2); // buf (kt+2)%3 == (kt-1)%3: safe after sync

        const uint32_t* A  = sA[kt % 3];
        const uint32_t* Bs = sB[kt % 3];

        uint4 afr[4][2];
        #pragma unroll
        for (int mi = 0; mi < 4; mi++)
            #pragma unroll
            for (int h = 0; h < 2; h++) {
                const int m = warp_m * 64 + mi * 16 + gid + 8 * h;
                afr[mi][h] = *(const uint4*)&A[m * 16 + fr_off];
            }

        #pragma unroll
        for (int ni = 0; ni < 4; ni++) {
            const int n = warp_n * 32 + ni * 8 + gid;
            const uint4 bv = *(const uint4*)&Bs[n * 16 + fr_off];
            #pragma unroll
            for (int mi = 0; mi < 4; mi++) {
                const uint32_t a0[4] = {afr[mi][0].x, afr[mi][1].x,
                                        afr[mi][0].y, afr[mi][1].y};
                const uint32_t b0[2] = {bv.x, bv.y};
                mma_tf32(acc[mi][ni], a0, b0);
                const uint32_t a1[4] = {afr[mi][0].z, afr[mi][1].z,
                                        afr[mi][0].w, afr[mi][1].w};
                const uint32_t b1[2] = {bv.z, bv.w};
                mma_tf32(acc[mi][ni], a1, b1);
            }
        }
        __syncthreads();                    // done with buf kt before it's refilled
    }

    // ---- epilogue: fused bias + sigmoid, float2 stores ----
    const int n0      = nblk * BN;           // 0..640
    const int region  = n0 >> 8;             // 0=xt, 1=f, 2=r
    float* dst        = (region == 0) ? g_xt : ((region == 1) ? g_f : g_r);
    const float* bias = (region == 1) ? bf : br;

    #pragma unroll
    for (int mi = 0; mi < 4; mi++) {
        const int row0 = mblk * BM + warp_m * 64 + mi * 16 + gid;
        #pragma unroll
        for (int ni = 0; ni < 4; ni++) {
            const int h = (n0 & (D_HALF - 1)) + warp_n * 32 + ni * 8 + 2 * tig;
            float v0 = acc[mi][ni][0], v1 = acc[mi][ni][1];
            float v2 = acc[mi][ni][2], v3 = acc[mi][ni][3];
            if (region != 0) {
                const float b0 = __ldg(bias + h), b1 = __ldg(bias + h + 1);
                v0 = sigmoidf_(v0 + b0);
                v1 = sigmoidf_(v1 + b1);
                v2 = sigmoidf_(v2 + b0);
                v3 = sigmoidf_(v3 + b1);
            }
            const size_t col = (size_t)s * D_HALF + h;
            *(float2*)(dst + (size_t)row0 * D_FULL + col)       = make_float2(v0, v1);
            *(float2*)(dst + (size_t)(row0 + 8) * D_FULL + col) = make_float2(v2, v3);
        }
    }
}

// ---------------------------------------------------------------------------
// Scan phase 1: per (b, chunk, c) local affine summary (P, C).
// ---------------------------------------------------------------------------
__global__ __launch_bounds__(256)
void scan_phase1(void)
{
    const int c     = blockIdx.x * 256 + threadIdx.x;
    const int chunk = blockIdx.y;
    const int b     = blockIdx.z;

    const size_t base = ((size_t)b * T_LEN + (size_t)chunk * CLEN) * D_FULL + c;
    const float* pf  = g_f  + base;
    const float* pxt = g_xt + base;

    float P = 1.0f, C = 0.0f;
    #pragma unroll 5
    for (int t = 0; t < CLEN; t++) {
        const size_t off = (size_t)t * D_FULL;
        const float f  = pf [off];
        const float xt = pxt[off];
        C = fmaf(f, C, (1.0f - f) * xt);
        P *= f;
    }
    const size_t sidx = ((size_t)b * NCHUNK + chunk) * D_FULL + c;
    g_P[sidx] = P;
    g_C[sidx] = C;
}

// ---------------------------------------------------------------------------
// Scan phase 2: serial scan over chunk summaries -> carry-in per chunk.
// ---------------------------------------------------------------------------
__global__ __launch_bounds__(256)
void scan_phase2(void)
{
    const int idx = blockIdx.x * 256 + threadIdx.x;
    const int b = idx >> 9;
    const int c = idx & (D_FULL - 1);

    float carry = 0.0f;
    #pragma unroll
    for (int k = 0; k < NCHUNK; k++) {
        const size_t sidx = ((size_t)b * NCHUNK + k) * D_FULL + c;
        g_cin[sidx] = carry;
        carry = fmaf(g_P[sidx], carry, g_C[sidx]);
    }
}

// ---------------------------------------------------------------------------
// Scan phase 3: recurrence from carry-in; fused highway output.
// ---------------------------------------------------------------------------
__global__ __launch_bounds__(256)
void scan_phase3(const float* __restrict__ x, float* __restrict__ out)
{
    const int c     = blockIdx.x * 256 + threadIdx.x;
    const int chunk = blockIdx.y;
    const int b     = blockIdx.z;

    const size_t base = ((size_t)b * T_LEN + (size_t)chunk * CLEN) * D_FULL + c;
    const float* pf  = g_f  + base;
    const float* pxt = g_xt + base;
    const float* pr  = g_r  + base;
    const float* px  = x    + base;
    float*       po  = out  + base;

    float cacc = g_cin[((size_t)b * NCHUNK + chunk) * D_FULL + c];

    #pragma unroll 5
    for (int t = 0; t < CLEN; t++) {
        const size_t off = (size_t)t * D_FULL;
        const float f  = pf [off];
        const float xt = pxt[off];
        const float r  = pr [off];
        const float xv = px [off];
        cacc = fmaf(f, cacc, (1.0f - f) * xt);
        po[off] = fmaf(r, cacc, (1.0f - r) * xv);
    }
}

// ---------------------------------------------------------------------------
extern "C" void kernel_launch(void* const* d_in, const int* in_sizes, int n_in,
                              void* d_out, int out_size)
{
    const float* x   = (const float*)d_in[0];
    const float* W1  = (const float*)d_in[1];
    const float* bf1 = (const float*)d_in[2];
    const float* br1 = (const float*)d_in[3];
    const float* W2  = (const float*)d_in[4];
    const float* bf2 = (const float*)d_in[5];
    const float* br2 = (const float*)d_in[6];
    float* out = (float*)d_out;

    (void)n_in; (void)in_sizes; (void)out_size;

    dim3 cxgrid(NKT, NMBLK, 2);                // (16, 500, 2)
    convert_x_kernel<<<cxgrid, 256>>>(x);
    dim3 cwgrid(NKT, 6, 2);                    // (16, 6, 2)
    convert_w_kernel<<<cwgrid, 256>>>(W1, W2);

    dim3 ggrid(12, NMBLK);                     // (12, 500)
    gemm_mma_kernel<<<ggrid, 256>>>(bf1, br1, bf2, br2);

    dim3 sgrid(2, NCHUNK, B_SZ);               // (2, 40, 32)
    scan_phase1<<<sgrid, 256>>>();
    scan_phase2<<<(B_SZ * D_FULL) / 256, 256>>>();
    scan_phase3<<<sgrid, 256>>>(x, out);
}

// round 9
// speedup vs baseline: 1.5644x; 1.2554x over previous
#include <cuda_runtime.h>
#include <cuda_fp16.h>
#include <cstdint>
#include <math.h>

// Shapes (fixed): B=32, T=2000, D=512, halves of 256, 3H=768.
#define M_TOTAL   64000
#define B_SZ      32
#define T_LEN     2000
#define D_FULL    512
#define D_HALF    256
#define N_COLS    768

// Scan chunking
#define NCHUNK 40
#define CLEN   50

// GEMM tiling (mma.sync m16n8k16 fp16)
#define BM 128
#define BN 128
#define BK 16
#define NKT (D_HALF / BK)        // 16 k-tiles
#define NMBLK (M_TOTAL / BM)     // 500
#define TILE_U32 1024            // 128 x 16 fp16 = 1024 uint32 = 4KB

// Scratch (device globals: allocation-free per harness rules).
__device__ float g_xt[M_TOTAL * D_FULL];
__device__ float g_f [M_TOTAL * D_FULL];
__device__ float g_r [M_TOTAL * D_FULL];
__device__ float g_P  [B_SZ * NCHUNK * D_FULL];
__device__ float g_C  [B_SZ * NCHUNK * D_FULL];
__device__ float g_cin[B_SZ * NCHUNK * D_FULL];
// pre-converted fp16 operand images in fragment-packed SMEM tile layout
__device__ uint32_t g_xc[2 * NMBLK * NKT * TILE_U32];   // 65.5 MB
__device__ uint32_t g_wc[2 * 6 * NKT * TILE_U32];       // 0.8 MB

__device__ __forceinline__ float sigmoidf_(float v) {
    return 1.0f / (1.0f + __expf(-v));
}

__device__ __forceinline__ uint32_t smem_u32(const void* p) {
    uint32_t a;
    asm("{ .reg .u64 t; cvta.to.shared.u64 t, %1; cvt.u32.u64 %0, t; }"
        : "=r"(a) : "l"(p));
    return a;
}

__device__ __forceinline__ uint32_t pack_h2(float lo, float hi) {
    __half2 h = __halves2half2(__float2half_rn(lo), __float2half_rn(hi));
    return *(uint32_t*)&h;
}

__device__ __forceinline__ void cp_async16(uint32_t smem_dst, const void* gptr) {
    asm volatile("cp.async.ca.shared.global [%0], [%1], 16;"
                 :: "r"(smem_dst), "l"(gptr) : "memory");
}
__device__ __forceinline__ void cp_async_commit() {
    asm volatile("cp.async.commit_group;" ::: "memory");
}
template <int N>
__device__ __forceinline__ void cp_async_wait() {
    asm volatile("cp.async.wait_group %0;" :: "n"(N) : "memory");
}

__device__ __forceinline__ void mma_f16(float* c, uint32_t a0, uint32_t a1,
                                        uint32_t a2, uint32_t a3,
                                        uint32_t b0, uint32_t b1) {
    asm volatile(
        "mma.sync.aligned.m16n8k16.row.col.f32.f16.f16.f32 "
        "{%0,%1,%2,%3}, {%4,%5,%6,%7}, {%8,%9}, {%0,%1,%2,%3};"
        : "+f"(c[0]), "+f"(c[1]), "+f"(c[2]), "+f"(c[3])
        : "r"(a0), "r"(a1), "r"(a2), "r"(a3), "r"(b0), "r"(b1));
}

// Fragment-packed A layout (uint32 = fp16x2 k-pair p = k>>1):
//   off(r,p) = (r>>4)*128 + (r&7)*16 + (p&3)*4 + ((r>>3)&1)*2 + (p>>2)
// => thread (gid,tig) of warp row-group mi: ONE uint4 at mi*128+gid*16+tig*4
//    gives {a0=(r_lo,p_lo), a2=(r_lo,p_hi), a1=(r_hi,p_lo), a3=(r_hi,p_hi)}.
__device__ __forceinline__ int a_off(int r, int p) {
    return ((r >> 4) << 7) + ((r & 7) << 4) + ((p & 3) << 2)
         + (((r >> 3) & 1) << 1) + (p >> 2);
}
// B layout: off(n,p) = n*8 + (p&3)*2 + (p>>2)
// => thread reads uint2 at n*8 + tig*2 giving {b0 (p=tig), b1 (p=tig+4)}.
__device__ __forceinline__ int b_off(int n, int p) {
    return (n << 3) + ((p & 3) << 1) + (p >> 2);
}

// ---------------------------------------------------------------------------
// Pre-pass A: x -> g_xc (fp16 pairs, tile-major [s][mblk][kt], packed layout).
// ---------------------------------------------------------------------------
__global__ __launch_bounds__(256)
void convert_x_kernel(const float* __restrict__ x)
{
    const int kt   = blockIdx.x;     // 0..15
    const int mblk = blockIdx.y;     // 0..499
    const int s    = blockIdx.z;     // 0..1

    const int tid = threadIdx.x;
    uint32_t* dst = g_xc + ((size_t)((s * NMBLK + mblk) * NKT + kt)) * TILE_U32;
    const float* src = x + (size_t)(mblk * BM) * D_FULL + s * D_HALF + kt * BK;

    #pragma unroll
    for (int j = 0; j < 2; j++) {
        const int idx = tid + 256 * j;        // 0..511
        const int row = idx >> 2;             // 0..127
        const int c4  = idx & 3;              // float4 chunk: k = 4*c4 .. 4*c4+3
        float4 v = *(const float4*)(src + (size_t)row * D_FULL + 4 * c4);
        dst[a_off(row, 2 * c4)]     = pack_h2(v.x, v.y);
        dst[a_off(row, 2 * c4 + 1)] = pack_h2(v.z, v.w);
    }
}

// ---------------------------------------------------------------------------
// Pre-pass B: W1/W2 -> g_wc (fp16 pairs, [s][nblk][kt], transposed to [n][k]).
// ---------------------------------------------------------------------------
__global__ __launch_bounds__(256)
void convert_w_kernel(const float* __restrict__ W1, const float* __restrict__ W2)
{
    const int kt   = blockIdx.x;     // 0..15
    const int nblk = blockIdx.y;     // 0..5
    const int s    = blockIdx.z;     // 0..1

    const int tid = threadIdx.x;
    const float* W = s ? W2 : W1;
    uint32_t* dst = g_wc + ((size_t)((s * 6 + nblk) * NKT + kt)) * TILE_U32;
    const float* src = W + (size_t)(kt * BK) * N_COLS + nblk * BN;

    #pragma unroll
    for (int j = 0; j < 4; j++) {
        const int idx = tid + 256 * j;        // 0..1023 = p*128 + n
        const int p = idx >> 7;               // k-pair 0..7
        const int n = idx & 127;
        const float w0 = src[(size_t)(2 * p)     * N_COLS + n];
        const float w1 = src[(size_t)(2 * p + 1) * N_COLS + n];
        dst[b_off(n, p)] = pack_h2(w0, w1);
    }
}

// ---------------------------------------------------------------------------
// Kernel 1: fp16 mma.sync (m16n8k16) GEMM from fragment-packed images.
// cp.async 3-stage pipeline; per thread per k-tile: 4 LDS.128 + 4 LDS.64 + 16 MMA.
// 8 warps = 2(m) x 4(n); warp tile 64x32 = 4x4 frags. Grid (12, 500), 256 thr.
// ---------------------------------------------------------------------------
__global__ __launch_bounds__(256, 2)
void gemm_mma_kernel(const float* __restrict__ bf1, const float* __restrict__ br1,
                     const float* __restrict__ bf2, const float* __restrict__ br2)
{
    const int s    = blockIdx.x / 6;     // half 0/1
    const int nblk = blockIdx.x % 6;     // 0..5
    const int mblk = blockIdx.y;         // 0..499

    const float* bf = s ? bf2 : bf1;
    const float* br = s ? br2 : br1;

    __shared__ uint32_t sA[3][TILE_U32];  // 3 x 4KB
    __shared__ uint32_t sB[3][TILE_U32];  // 3 x 4KB

    const int tid    = threadIdx.x;
    const int wid    = tid >> 5;
    const int lid    = tid & 31;
    const int gid    = lid >> 2;         // 0..7
    const int tig    = lid & 3;          // 0..3
    const int warp_m = wid >> 2;         // 0..1
    const int warp_n = wid & 3;          // 0..3

    const uint32_t* Asrc = g_xc + ((size_t)(s * NMBLK + mblk)) * NKT * TILE_U32;
    const uint32_t* Bsrc = g_wc + ((size_t)(s * 6 + nblk)) * NKT * TILE_U32;

    auto prefetch = [&](int kt) {
        const int buf = kt % 3;
        const int e = tid * 4;              // 1024 uint32 per tile, 1 uint4/thread
        cp_async16(smem_u32(&sA[buf][e]), Asrc + (size_t)kt * TILE_U32 + e);
        cp_async16(smem_u32(&sB[buf][e]), Bsrc + (size_t)kt * TILE_U32 + e);
        cp_async_commit();
    };

    float acc[4][4][4];
    #pragma unroll
    for (int mi = 0; mi < 4; mi++)
        #pragma unroll
        for (int ni = 0; ni < 4; ni++)
            #pragma unroll
            for (int q = 0; q < 4; q++) acc[mi][ni][q] = 0.0f;

    prefetch(0);
    prefetch(1);

    #pragma unroll 1
    for (int kt = 0; kt < NKT; kt++) {
        // tail: last committed group is NKT-1; drain fully on final iter (R6 lesson)
        if (kt + 1 < NKT) cp_async_wait<1>();
        else              cp_async_wait<0>();
        __syncthreads();
        if (kt + 2 < NKT) prefetch(kt + 2);   // refills buf (kt-1)%3: safe after sync

        const uint32_t* A  = sA[kt % 3];
        const uint32_t* Bs = sB[kt % 3];

        uint4 afr[4];
        #pragma unroll
        for (int mi = 0; mi < 4; mi++)
            afr[mi] = *(const uint4*)&A[(warp_m * 4 + mi) * 128 + gid * 16 + tig * 4];

        #pragma unroll
        for (int ni = 0; ni < 4; ni++) {
            const int n = warp_n * 32 + ni * 8 + gid;
            const uint2 bv = *(const uint2*)&Bs[n * 8 + tig * 2];
            #pragma unroll
            for (int mi = 0; mi < 4; mi++)
                // afr = {a0, a2, a1, a3} -> operand order a0,a1,a2,a3
                mma_f16(acc[mi][ni], afr[mi].x, afr[mi].z, afr[mi].y, afr[mi].w,
                        bv.x, bv.y);
        }
        __syncthreads();
    }

    // ---- epilogue: fused bias + sigmoid, float2 stores (C layout unchanged) ----
    const int n0      = nblk * BN;           // 0..640
    const int region  = n0 >> 8;             // 0=xt, 1=f, 2=r
    float* dst        = (region == 0) ? g_xt : ((region == 1) ? g_f : g_r);
    const float* bias = (region == 1) ? bf : br;

    #pragma unroll
    for (int mi = 0; mi < 4; mi++) {
        const int row0 = mblk * BM + warp_m * 64 + mi * 16 + gid;
        #pragma unroll
        for (int ni = 0; ni < 4; ni++) {
            const int h = (n0 & (D_HALF - 1)) + warp_n * 32 + ni * 8 + 2 * tig;
            float v0 = acc[mi][ni][0], v1 = acc[mi][ni][1];
            float v2 = acc[mi][ni][2], v3 = acc[mi][ni][3];
            if (region != 0) {
                const float b0 = __ldg(bias + h), b1 = __ldg(bias + h + 1);
                v0 = sigmoidf_(v0 + b0);
                v1 = sigmoidf_(v1 + b1);
                v2 = sigmoidf_(v2 + b0);
                v3 = sigmoidf_(v3 + b1);
            }
            const size_t col = (size_t)s * D_HALF + h;
            *(float2*)(dst + (size_t)row0 * D_FULL + col)       = make_float2(v0, v1);
            *(float2*)(dst + (size_t)(row0 + 8) * D_FULL + col) = make_float2(v2, v3);
        }
    }
}

// ---------------------------------------------------------------------------
// Scan phase 1: per (b, chunk, c) local affine summary (P, C).
// ---------------------------------------------------------------------------
__global__ __launch_bounds__(256)
void scan_phase1(void)
{
    const int c     = blockIdx.x * 256 + threadIdx.x;
    const int chunk = blockIdx.y;
    const int b     = blockIdx.z;

    const size_t base = ((size_t)b * T_LEN + (size_t)chunk * CLEN) * D_FULL + c;
    const float* pf  = g_f  + base;
    const float* pxt = g_xt + base;

    float P = 1.0f, C = 0.0f;
    #pragma unroll 5
    for (int t = 0; t < CLEN; t++) {
        const size_t off = (size_t)t * D_FULL;
        const float f  = pf [off];
        const float xt = pxt[off];
        C = fmaf(f, C, (1.0f - f) * xt);
        P *= f;
    }
    const size_t sidx = ((size_t)b * NCHUNK + chunk) * D_FULL + c;
    g_P[sidx] = P;
    g_C[sidx] = C;
}

// ---------------------------------------------------------------------------
// Scan phase 2: serial scan over chunk summaries -> carry-in per chunk.
// ---------------------------------------------------------------------------
__global__ __launch_bounds__(256)
void scan_phase2(void)
{
    const int idx = blockIdx.x * 256 + threadIdx.x;
    const int b = idx >> 9;
    const int c = idx & (D_FULL - 1);

    float carry = 0.0f;
    #pragma unroll
    for (int k = 0; k < NCHUNK; k++) {
        const size_t sidx = ((size_t)b * NCHUNK + k) * D_FULL + c;
        g_cin[sidx] = carry;
        carry = fmaf(g_P[sidx], carry, g_C[sidx]);
    }
}

// ---------------------------------------------------------------------------
// Scan phase 3: recurrence from carry-in; fused highway output.
// ---------------------------------------------------------------------------
__global__ __launch_bounds__(256)
void scan_phase3(const float* __restrict__ x, float* __restrict__ out)
{
    const int c     = blockIdx.x * 256 + threadIdx.x;
    const int chunk = blockIdx.y;
    const int b     = blockIdx.z;

    const size_t base = ((size_t)b * T_LEN + (size_t)chunk * CLEN) * D_FULL + c;
    const float* pf  = g_f  + base;
    const float* pxt = g_xt + base;
    const float* pr  = g_r  + base;
    const float* px  = x    + base;
    float*       po  = out  + base;

    float cacc = g_cin[((size_t)b * NCHUNK + chunk) * D_FULL + c];

    #pragma unroll 5
    for (int t = 0; t < CLEN; t++) {
        const size_t off = (size_t)t * D_FULL;
        const float f  = pf [off];
        const float xt = pxt[off];
        const float r  = pr [off];
        const float xv = px [off];
        cacc = fmaf(f, cacc, (1.0f - f) * xt);
        po[off] = fmaf(r, cacc, (1.0f - r) * xv);
    }
}

// ---------------------------------------------------------------------------
extern "C" void kernel_launch(void* const* d_in, const int* in_sizes, int n_in,
                              void* d_out, int out_size)
{
    const float* x   = (const float*)d_in[0];
    const float* W1  = (const float*)d_in[1];
    const float* bf1 = (const float*)d_in[2];
    const float* br1 = (const float*)d_in[3];
    const float* W2  = (const float*)d_in[4];
    const float* bf2 = (const float*)d_in[5];
    const float* br2 = (const float*)d_in[6];
    float* out = (float*)d_out;

    (void)n_in; (void)in_sizes; (void)out_size;

    dim3 cxgrid(NKT, NMBLK, 2);                // (16, 500, 2)
    convert_x_kernel<<<cxgrid, 256>>>(x);
    dim3 cwgrid(NKT, 6, 2);                    // (16, 6, 2)
    convert_w_kernel<<<cwgrid, 256>>>(W1, W2);

    dim3 ggrid(12, NMBLK);                     // (12, 500)
    gemm_mma_kernel<<<ggrid, 256>>>(bf1, br1, bf2, br2);

    dim3 sgrid(2, NCHUNK, B_SZ);               // (2, 40, 32)
    scan_phase1<<<sgrid, 256>>>();
    scan_phase2<<<(B_SZ * D_FULL) / 256, 256>>>();
    scan_phase3<<<sgrid, 256>>>(x, out);
}

// round 10
// speedup vs baseline: 1.7521x; 1.1200x over previous
#include <cuda_runtime.h>
#include <cuda_fp16.h>
#include <cstdint>
#include <math.h>

// Shapes (fixed): B=32, T=2000, D=512, halves of 256, 3H=768.
#define M_TOTAL   64000
#define B_SZ      32
#define T_LEN     2000
#define D_FULL    512
#define D_HALF2   256            // D_FULL in half2 units
#define N_COLS    768

// Scan chunking
#define NCHUNK 40
#define CLEN   50

// GEMM tiling (mma.sync m16n8k16 fp16)
#define BM 128
#define BN 128
#define BK 16
#define NKT (D_HALF / BK)
#define D_HALF 256
#define NMBLK (M_TOTAL / BM)     // 500
#define TILE_U32 1024            // 128 x 16 fp16 = 4KB

// Scratch (device globals: allocation-free per harness rules).
// Gates / x-tilde stored as fp16 (half2-addressable).
__device__ __half2 g_xt[M_TOTAL * D_HALF2];
__device__ __half2 g_f [M_TOTAL * D_HALF2];
__device__ __half2 g_r [M_TOTAL * D_HALF2];
__device__ float g_P  [B_SZ * NCHUNK * D_FULL];
__device__ float g_C  [B_SZ * NCHUNK * D_FULL];
__device__ float g_cin[B_SZ * NCHUNK * D_FULL];
// pre-converted fp16 operand images in fragment-packed SMEM tile layout
__device__ uint32_t g_xc[2 * NMBLK * (D_HALF / BK) * TILE_U32];   // 65.5 MB
__device__ uint32_t g_wc[2 * 6 * (D_HALF / BK) * TILE_U32];       // 0.8 MB

__device__ __forceinline__ float sigmoidf_(float v) {
    return 1.0f / (1.0f + __expf(-v));
}

__device__ __forceinline__ uint32_t smem_u32(const void* p) {
    uint32_t a;
    asm("{ .reg .u64 t; cvta.to.shared.u64 t, %1; cvt.u32.u64 %0, t; }"
        : "=r"(a) : "l"(p));
    return a;
}

__device__ __forceinline__ uint32_t pack_h2(float lo, float hi) {
    __half2 h = __halves2half2(__float2half_rn(lo), __float2half_rn(hi));
    return *(uint32_t*)&h;
}

__device__ __forceinline__ void cp_async16(uint32_t smem_dst, const void* gptr) {
    asm volatile("cp.async.ca.shared.global [%0], [%1], 16;"
                 :: "r"(smem_dst), "l"(gptr) : "memory");
}
__device__ __forceinline__ void cp_async_commit() {
    asm volatile("cp.async.commit_group;" ::: "memory");
}
template <int N>
__device__ __forceinline__ void cp_async_wait() {
    asm volatile("cp.async.wait_group %0;" :: "n"(N) : "memory");
}

__device__ __forceinline__ void mma_f16(float* c, uint32_t a0, uint32_t a1,
                                        uint32_t a2, uint32_t a3,
                                        uint32_t b0, uint32_t b1) {
    asm volatile(
        "mma.sync.aligned.m16n8k16.row.col.f32.f16.f16.f32 "
        "{%0,%1,%2,%3}, {%4,%5,%6,%7}, {%8,%9}, {%0,%1,%2,%3};"
        : "+f"(c[0]), "+f"(c[1]), "+f"(c[2]), "+f"(c[3])
        : "r"(a0), "r"(a1), "r"(a2), "r"(a3), "r"(b0), "r"(b1));
}

// Fragment-packed layouts (validated R8):
__device__ __forceinline__ int a_off(int r, int p) {
    return ((r >> 4) << 7) + ((r & 7) << 4) + ((p & 3) << 2)
         + (((r >> 3) & 1) << 1) + (p >> 2);
}
__device__ __forceinline__ int b_off(int n, int p) {
    return (n << 3) + ((p & 3) << 1) + (p >> 2);
}

// ---------------------------------------------------------------------------
// Pre-pass A: x -> g_xc (fp16 pairs, tile-major, fragment-packed).
// ---------------------------------------------------------------------------
__global__ __launch_bounds__(256)
void convert_x_kernel(const float* __restrict__ x)
{
    const int kt   = blockIdx.x;
    const int mblk = blockIdx.y;
    const int s    = blockIdx.z;

    const int tid = threadIdx.x;
    uint32_t* dst = g_xc + ((size_t)((s * NMBLK + mblk) * NKT + kt)) * TILE_U32;
    const float* src = x + (size_t)(mblk * BM) * D_FULL + s * D_HALF + kt * BK;

    #pragma unroll
    for (int j = 0; j < 2; j++) {
        const int idx = tid + 256 * j;        // 0..511
        const int row = idx >> 2;
        const int c4  = idx & 3;
        float4 v = *(const float4*)(src + (size_t)row * D_FULL + 4 * c4);
        dst[a_off(row, 2 * c4)]     = pack_h2(v.x, v.y);
        dst[a_off(row, 2 * c4 + 1)] = pack_h2(v.z, v.w);
    }
}

// ---------------------------------------------------------------------------
// Pre-pass B: W1/W2 -> g_wc (fp16 pairs, transposed to [n][k]).
// ---------------------------------------------------------------------------
__global__ __launch_bounds__(256)
void convert_w_kernel(const float* __restrict__ W1, const float* __restrict__ W2)
{
    const int kt   = blockIdx.x;
    const int nblk = blockIdx.y;
    const int s    = blockIdx.z;

    const int tid = threadIdx.x;
    const float* W = s ? W2 : W1;
    uint32_t* dst = g_wc + ((size_t)((s * 6 + nblk) * NKT + kt)) * TILE_U32;
    const float* src = W + (size_t)(kt * BK) * N_COLS + nblk * BN;

    #pragma unroll
    for (int j = 0; j < 4; j++) {
        const int idx = tid + 256 * j;        // p*128 + n
        const int p = idx >> 7;
        const int n = idx & 127;
        const float w0 = src[(size_t)(2 * p)     * N_COLS + n];
        const float w1 = src[(size_t)(2 * p + 1) * N_COLS + n];
        dst[b_off(n, p)] = pack_h2(w0, w1);
    }
}

// ---------------------------------------------------------------------------
// Kernel 1: fp16 mma.sync (m16n8k16) GEMM. Epilogue writes half2 gates.
// ---------------------------------------------------------------------------
__global__ __launch_bounds__(256, 2)
void gemm_mma_kernel(const float* __restrict__ bf1, const float* __restrict__ br1,
                     const float* __restrict__ bf2, const float* __restrict__ br2)
{
    const int s    = blockIdx.x / 6;
    const int nblk = blockIdx.x % 6;
    const int mblk = blockIdx.y;

    const float* bf = s ? bf2 : bf1;
    const float* br = s ? br2 : br1;

    __shared__ uint32_t sA[3][TILE_U32];
    __shared__ uint32_t sB[3][TILE_U32];

    const int tid    = threadIdx.x;
    const int wid    = tid >> 5;
    const int lid    = tid & 31;
    const int gid    = lid >> 2;
    const int tig    = lid & 3;
    const int warp_m = wid >> 2;
    const int warp_n = wid & 3;

    const uint32_t* Asrc = g_xc + ((size_t)(s * NMBLK + mblk)) * NKT * TILE_U32;
    const uint32_t* Bsrc = g_wc + ((size_t)(s * 6 + nblk)) * NKT * TILE_U32;

    auto prefetch = [&](int kt) {
        const int buf = kt % 3;
        const int e = tid * 4;
        cp_async16(smem_u32(&sA[buf][e]), Asrc + (size_t)kt * TILE_U32 + e);
        cp_async16(smem_u32(&sB[buf][e]), Bsrc + (size_t)kt * TILE_U32 + e);
        cp_async_commit();
    };

    float acc[4][4][4];
    #pragma unroll
    for (int mi = 0; mi < 4; mi++)
        #pragma unroll
        for (int ni = 0; ni < 4; ni++)
            #pragma unroll
            for (int q = 0; q < 4; q++) acc[mi][ni][q] = 0.0f;

    prefetch(0);
    prefetch(1);

    #pragma unroll 1
    for (int kt = 0; kt < NKT; kt++) {
        if (kt + 1 < NKT) cp_async_wait<1>();
        else              cp_async_wait<0>();
        __syncthreads();
        if (kt + 2 < NKT) prefetch(kt + 2);

        const uint32_t* A  = sA[kt % 3];
        const uint32_t* Bs = sB[kt % 3];

        uint4 afr[4];
        #pragma unroll
        for (int mi = 0; mi < 4; mi++)
            afr[mi] = *(const uint4*)&A[(warp_m * 4 + mi) * 128 + gid * 16 + tig * 4];

        #pragma unroll
        for (int ni = 0; ni < 4; ni++) {
            const int n = warp_n * 32 + ni * 8 + gid;
            const uint2 bv = *(const uint2*)&Bs[n * 8 + tig * 2];
            #pragma unroll
            for (int mi = 0; mi < 4; mi++)
                mma_f16(acc[mi][ni], afr[mi].x, afr[mi].z, afr[mi].y, afr[mi].w,
                        bv.x, bv.y);
        }
        __syncthreads();
    }

    // ---- epilogue: fused bias + sigmoid, half2 stores ----
    const int n0      = nblk * BN;
    const int region  = n0 >> 8;             // 0=xt, 1=f, 2=r
    __half2* dst      = (region == 0) ? g_xt : ((region == 1) ? g_f : g_r);
    const float* bias = (region == 1) ? bf : br;

    #pragma unroll
    for (int mi = 0; mi < 4; mi++) {
        const int row0 = mblk * BM + warp_m * 64 + mi * 16 + gid;
        #pragma unroll
        for (int ni = 0; ni < 4; ni++) {
            const int h = (n0 & (D_HALF - 1)) + warp_n * 32 + ni * 8 + 2 * tig;
            float v0 = acc[mi][ni][0], v1 = acc[mi][ni][1];
            float v2 = acc[mi][ni][2], v3 = acc[mi][ni][3];
            if (region != 0) {
                const float b0 = __ldg(bias + h), b1 = __ldg(bias + h + 1);
                v0 = sigmoidf_(v0 + b0);
                v1 = sigmoidf_(v1 + b1);
                v2 = sigmoidf_(v2 + b0);
                v3 = sigmoidf_(v3 + b1);
            }
            const size_t cp = (size_t)(s * D_HALF + h) >> 1;   // half2 column
            dst[(size_t)row0 * D_HALF2 + cp]       = __floats2half2_rn(v0, v1);
            dst[(size_t)(row0 + 8) * D_HALF2 + cp] = __floats2half2_rn(v2, v3);
        }
    }
}

// ---------------------------------------------------------------------------
// Scan phase 1: one thread per channel PAIR (half2); float2 carries.
// Grid (1, NCHUNK, B_SZ), 256 threads.
// ---------------------------------------------------------------------------
__global__ __launch_bounds__(256)
void scan_phase1(void)
{
    const int c2    = threadIdx.x;        // 0..255 (channel pair)
    const int chunk = blockIdx.y;
    const int b     = blockIdx.z;

    const size_t base = ((size_t)b * T_LEN + (size_t)chunk * CLEN) * D_HALF2 + c2;
    const __half2* pf  = g_f  + base;
    const __half2* pxt = g_xt + base;

    float2 P = make_float2(1.0f, 1.0f);
    float2 C = make_float2(0.0f, 0.0f);
    #pragma unroll 5
    for (int t = 0; t < CLEN; t++) {
        const size_t off = (size_t)t * D_HALF2;
        const float2 f  = __half22float2(pf [off]);
        const float2 xt = __half22float2(pxt[off]);
        C.x = fmaf(f.x, C.x, (1.0f - f.x) * xt.x);
        C.y = fmaf(f.y, C.y, (1.0f - f.y) * xt.y);
        P.x *= f.x;
        P.y *= f.y;
    }
    const size_t sidx = ((size_t)b * NCHUNK + chunk) * (D_FULL / 2) + c2;
    *(float2*)&g_P[2 * sidx] = P;
    *(float2*)&g_C[2 * sidx] = C;
}

// ---------------------------------------------------------------------------
// Scan phase 2: serial scan over chunk summaries -> carry-in per chunk.
// ---------------------------------------------------------------------------
__global__ __launch_bounds__(256)
void scan_phase2(void)
{
    const int idx = blockIdx.x * 256 + threadIdx.x;   // 0..16383
    const int b = idx >> 9;
    const int c = idx & (D_FULL - 1);

    float carry = 0.0f;
    #pragma unroll
    for (int k = 0; k < NCHUNK; k++) {
        const size_t sidx = ((size_t)b * NCHUNK + k) * D_FULL + c;
        g_cin[sidx] = carry;
        carry = fmaf(g_P[sidx], carry, g_C[sidx]);
    }
}

// ---------------------------------------------------------------------------
// Scan phase 3: recurrence from carry-in; fused highway output (float2).
// Grid (1, NCHUNK, B_SZ), 256 threads (one per channel pair).
// ---------------------------------------------------------------------------
__global__ __launch_bounds__(256)
void scan_phase3(const float* __restrict__ x, float* __restrict__ out)
{
    const int c2    = threadIdx.x;
    const int chunk = blockIdx.y;
    const int b     = blockIdx.z;

    const size_t base = ((size_t)b * T_LEN + (size_t)chunk * CLEN) * D_HALF2 + c2;
    const __half2* pf  = g_f  + base;
    const __half2* pxt = g_xt + base;
    const __half2* pr  = g_r  + base;
    const float2*  px  = (const float2*)x   + base;   // same indexing in float2 units
    float2*        po  = (float2*)out        + base;

    float2 cacc = *(const float2*)&g_cin[2 * (((size_t)b * NCHUNK + chunk) * (D_FULL / 2) + c2)];

    #pragma unroll 5
    for (int t = 0; t < CLEN; t++) {
        const size_t off = (size_t)t * D_HALF2;
        const float2 f  = __half22float2(pf [off]);
        const float2 xt = __half22float2(pxt[off]);
        const float2 r  = __half22float2(pr [off]);
        const float2 xv = px[off];
        cacc.x = fmaf(f.x, cacc.x, (1.0f - f.x) * xt.x);
        cacc.y = fmaf(f.y, cacc.y, (1.0f - f.y) * xt.y);
        float2 h;
        h.x = fmaf(r.x, cacc.x, (1.0f - r.x) * xv.x);
        h.y = fmaf(r.y, cacc.y, (1.0f - r.y) * xv.y);
        po[off] = h;
    }
}

// ---------------------------------------------------------------------------
extern "C" void kernel_launch(void* const* d_in, const int* in_sizes, int n_in,
                              void* d_out, int out_size)
{
    const float* x   = (const float*)d_in[0];
    const float* W1  = (const float*)d_in[1];
    const float* bf1 = (const float*)d_in[2];
    const float* br1 = (const float*)d_in[3];
    const float* W2  = (const float*)d_in[4];
    const float* bf2 = (const float*)d_in[5];
    const float* br2 = (const float*)d_in[6];
    float* out = (float*)d_out;

    (void)n_in; (void)in_sizes; (void)out_size;

    dim3 cxgrid(NKT, NMBLK, 2);                // (16, 500, 2)
    convert_x_kernel<<<cxgrid, 256>>>(x);
    dim3 cwgrid(NKT, 6, 2);                    // (16, 6, 2)
    convert_w_kernel<<<cwgrid, 256>>>(W1, W2);

    dim3 ggrid(12, NMBLK);                     // (12, 500)
    gemm_mma_kernel<<<ggrid, 256>>>(bf1, br1, bf2, br2);

    dim3 sgrid(1, NCHUNK, B_SZ);               // (1, 40, 32)
    scan_phase1<<<sgrid, 256>>>();
    scan_phase2<<<(B_SZ * D_FULL) / 256, 256>>>();
    scan_phase3<<<sgrid, 256>>>(x, out);
}

// round 11
// speedup vs baseline: 1.8615x; 1.0625x over previous
#include <cuda_runtime.h>
#include <cuda_fp16.h>
#include <cstdint>
#include <math.h>

// Shapes (fixed): B=32, T=2000, D=512, halves of 256, 3H=768.
#define M_TOTAL   64000
#define B_SZ      32
#define T_LEN     2000
#define D_FULL    512
#define D_HALF    256
#define D_HALF2   256            // D_FULL in half2 units
#define N_COLS    768

// Scan chunking
#define NCHUNK 40
#define CLEN   50

// GEMM tiling (mma.sync m16n8k16 fp16)
#define BM 128
#define BN 128
#define BK 16
#define NKT (D_HALF / BK)        // 16 k-tiles
#define NST (NKT / 2)            // 8 supertiles (BK=32 staging)
#define NMBLK (M_TOTAL / BM)     // 500
#define TILE_U32 1024            // 128 x 16 fp16 = 4KB
#define STILE_U32 (2 * TILE_U32) // supertile = 8KB

// Scratch (device globals: allocation-free per harness rules).
__device__ __half2 g_xt[M_TOTAL * D_HALF2];
__device__ __half2 g_f [M_TOTAL * D_HALF2];
__device__ __half2 g_r [M_TOTAL * D_HALF2];
__device__ float g_P  [B_SZ * NCHUNK * D_FULL];
__device__ float g_C  [B_SZ * NCHUNK * D_FULL];
__device__ float g_cin[B_SZ * NCHUNK * D_FULL];
// pre-converted fp16 operand images in fragment-packed SMEM tile layout
__device__ uint32_t g_xc[2 * NMBLK * NKT * TILE_U32];   // 65.5 MB
__device__ uint32_t g_wc[2 * 6 * NKT * TILE_U32];       // 0.8 MB

__device__ __forceinline__ float sigmoidf_(float v) {
    return 1.0f / (1.0f + __expf(-v));
}

__device__ __forceinline__ uint32_t smem_u32(const void* p) {
    uint32_t a;
    asm("{ .reg .u64 t; cvta.to.shared.u64 t, %1; cvt.u32.u64 %0, t; }"
        : "=r"(a) : "l"(p));
    return a;
}

__device__ __forceinline__ uint32_t pack_h2(float lo, float hi) {
    __half2 h = __halves2half2(__float2half_rn(lo), __float2half_rn(hi));
    return *(uint32_t*)&h;
}

__device__ __forceinline__ void cp_async16(uint32_t smem_dst, const void* gptr) {
    asm volatile("cp.async.ca.shared.global [%0], [%1], 16;"
                 :: "r"(smem_dst), "l"(gptr) : "memory");
}
__device__ __forceinline__ void cp_async_commit() {
    asm volatile("cp.async.commit_group;" ::: "memory");
}
template <int N>
__device__ __forceinline__ void cp_async_wait() {
    asm volatile("cp.async.wait_group %0;" :: "n"(N) : "memory");
}

__device__ __forceinline__ void mma_f16(float* c, uint32_t a0, uint32_t a1,
                                        uint32_t a2, uint32_t a3,
                                        uint32_t b0, uint32_t b1) {
    asm volatile(
        "mma.sync.aligned.m16n8k16.row.col.f32.f16.f16.f32 "
        "{%0,%1,%2,%3}, {%4,%5,%6,%7}, {%8,%9}, {%0,%1,%2,%3};"
        : "+f"(c[0]), "+f"(c[1]), "+f"(c[2]), "+f"(c[3])
        : "r"(a0), "r"(a1), "r"(a2), "r"(a3), "r"(b0), "r"(b1));
}

// Fragment-packed layouts (validated R8/R9):
__device__ __forceinline__ int a_off(int r, int p) {
    return ((r >> 4) << 7) + ((r & 7) << 4) + ((p & 3) << 2)
         + (((r >> 3) & 1) << 1) + (p >> 2);
}
__device__ __forceinline__ int b_off(int n, int p) {
    return (n << 3) + ((p & 3) << 1) + (p >> 2);
}

// ---------------------------------------------------------------------------
// Pre-pass A: x -> g_xc (fp16 pairs, tile-major, fragment-packed).
// ---------------------------------------------------------------------------
__global__ __launch_bounds__(256)
void convert_x_kernel(const float* __restrict__ x)
{
    const int kt   = blockIdx.x;
    const int mblk = blockIdx.y;
    const int s    = blockIdx.z;

    const int tid = threadIdx.x;
    uint32_t* dst = g_xc + ((size_t)((s * NMBLK + mblk) * NKT + kt)) * TILE_U32;
    const float* src = x + (size_t)(mblk * BM) * D_FULL + s * D_HALF + kt * BK;

    #pragma unroll
    for (int j = 0; j < 2; j++) {
        const int idx = tid + 256 * j;        // 0..511
        const int row = idx >> 2;
        const int c4  = idx & 3;
        float4 v = *(const float4*)(src + (size_t)row * D_FULL + 4 * c4);
        dst[a_off(row, 2 * c4)]     = pack_h2(v.x, v.y);
        dst[a_off(row, 2 * c4 + 1)] = pack_h2(v.z, v.w);
    }
}

// ---------------------------------------------------------------------------
// Pre-pass B: W1/W2 -> g_wc (fp16 pairs, transposed to [n][k]).
// ---------------------------------------------------------------------------
__global__ __launch_bounds__(256)
void convert_w_kernel(const float* __restrict__ W1, const float* __restrict__ W2)
{
    const int kt   = blockIdx.x;
    const int nblk = blockIdx.y;
    const int s    = blockIdx.z;

    const int tid = threadIdx.x;
    const float* W = s ? W2 : W1;
    uint32_t* dst = g_wc + ((size_t)((s * 6 + nblk) * NKT + kt)) * TILE_U32;
    const float* src = W + (size_t)(kt * BK) * N_COLS + nblk * BN;

    #pragma unroll
    for (int j = 0; j < 4; j++) {
        const int idx = tid + 256 * j;        // p*128 + n
        const int p = idx >> 7;
        const int n = idx & 127;
        const float w0 = src[(size_t)(2 * p)     * N_COLS + n];
        const float w1 = src[(size_t)(2 * p + 1) * N_COLS + n];
        dst[b_off(n, p)] = pack_h2(w0, w1);
    }
}

// ---------------------------------------------------------------------------
// Kernel 1: fp16 mma.sync (m16n8k16) GEMM.
// Supertile (BK=32) cp.async staging, 3-stage, ONE sync per supertile.
// Per supertile per thread: 2x(4 LDS.128 + 4 LDS.64 + 16 MMA).
// ---------------------------------------------------------------------------
__global__ __launch_bounds__(256, 2)
void gemm_mma_kernel(const float* __restrict__ bf1, const float* __restrict__ br1,
                     const float* __restrict__ bf2, const float* __restrict__ br2)
{
    const int s    = blockIdx.x / 6;
    const int nblk = blockIdx.x % 6;
    const int mblk = blockIdx.y;

    const float* bf = s ? bf2 : bf1;
    const float* br = s ? br2 : br1;

    __shared__ uint32_t sA[3][STILE_U32];  // 3 x 8KB
    __shared__ uint32_t sB[3][STILE_U32];  // 3 x 8KB

    const int tid    = threadIdx.x;
    const int wid    = tid >> 5;
    const int lid    = tid & 31;
    const int gid    = lid >> 2;
    const int tig    = lid & 3;
    const int warp_m = wid >> 2;
    const int warp_n = wid & 3;

    const uint32_t* Asrc = g_xc + ((size_t)(s * NMBLK + mblk)) * NKT * TILE_U32;
    const uint32_t* Bsrc = g_wc + ((size_t)(s * 6 + nblk)) * NKT * TILE_U32;

    auto prefetch = [&](int st) {               // supertile index 0..7
        const int buf = st % 3;
        const int e0 = tid * 4;
        const int e1 = tid * 4 + TILE_U32;
        const uint32_t* ga = Asrc + (size_t)st * STILE_U32;
        const uint32_t* gb = Bsrc + (size_t)st * STILE_U32;
        cp_async16(smem_u32(&sA[buf][e0]), ga + e0);
        cp_async16(smem_u32(&sA[buf][e1]), ga + e1);
        cp_async16(smem_u32(&sB[buf][e0]), gb + e0);
        cp_async16(smem_u32(&sB[buf][e1]), gb + e1);
        cp_async_commit();
    };

    float acc[4][4][4];
    #pragma unroll
    for (int mi = 0; mi < 4; mi++)
        #pragma unroll
        for (int ni = 0; ni < 4; ni++)
            #pragma unroll
            for (int q = 0; q < 4; q++) acc[mi][ni][q] = 0.0f;

    prefetch(0);
    prefetch(1);

    #pragma unroll 1
    for (int st = 0; st < NST; st++) {
        // tail (R6 lesson): last commit is supertile NST-1 (issued at iter NST-3);
        // at the final iters it may be the newest outstanding group — drain fully.
        if (st + 1 < NST) cp_async_wait<1>();
        else              cp_async_wait<0>();
        __syncthreads();   // (a) supertile st resident, (b) all threads done with
                           // compute st-1 -> safe to refill buf (st+2)%3 == (st-1)%3
        if (st + 2 < NST) prefetch(st + 2);

        #pragma unroll
        for (int sub = 0; sub < 2; sub++) {
            const uint32_t* A  = &sA[st % 3][sub * TILE_U32];
            const uint32_t* Bs = &sB[st % 3][sub * TILE_U32];

            uint4 afr[4];
            #pragma unroll
            for (int mi = 0; mi < 4; mi++)
                afr[mi] = *(const uint4*)&A[(warp_m * 4 + mi) * 128 + gid * 16 + tig * 4];

            #pragma unroll
            for (int ni = 0; ni < 4; ni++) {
                const int n = warp_n * 32 + ni * 8 + gid;
                const uint2 bv = *(const uint2*)&Bs[n * 8 + tig * 2];
                #pragma unroll
                for (int mi = 0; mi < 4; mi++)
                    mma_f16(acc[mi][ni], afr[mi].x, afr[mi].z, afr[mi].y, afr[mi].w,
                            bv.x, bv.y);
            }
        }
        // no second sync: next iteration's top sync provides the needed guarantee
    }

    // ---- epilogue: fused bias + sigmoid, half2 stores ----
    const int n0      = nblk * BN;
    const int region  = n0 >> 8;             // 0=xt, 1=f, 2=r
    __half2* dst      = (region == 0) ? g_xt : ((region == 1) ? g_f : g_r);
    const float* bias = (region == 1) ? bf : br;

    #pragma unroll
    for (int mi = 0; mi < 4; mi++) {
        const int row0 = mblk * BM + warp_m * 64 + mi * 16 + gid;
        #pragma unroll
        for (int ni = 0; ni < 4; ni++) {
            const int h = (n0 & (D_HALF - 1)) + warp_n * 32 + ni * 8 + 2 * tig;
            float v0 = acc[mi][ni][0], v1 = acc[mi][ni][1];
            float v2 = acc[mi][ni][2], v3 = acc[mi][ni][3];
            if (region != 0) {
                const float b0 = __ldg(bias + h), b1 = __ldg(bias + h + 1);
                v0 = sigmoidf_(v0 + b0);
                v1 = sigmoidf_(v1 + b1);
                v2 = sigmoidf_(v2 + b0);
                v3 = sigmoidf_(v3 + b1);
            }
            const size_t cp = (size_t)(s * D_HALF + h) >> 1;   // half2 column
            dst[(size_t)row0 * D_HALF2 + cp]       = __floats2half2_rn(v0, v1);
            dst[(size_t)(row0 + 8) * D_HALF2 + cp] = __floats2half2_rn(v2, v3);
        }
    }
}

// ---------------------------------------------------------------------------
// Scan phase 1: one thread per channel PAIR (half2); float2 carries.
// ---------------------------------------------------------------------------
__global__ __launch_bounds__(256)
void scan_phase1(void)
{
    const int c2    = threadIdx.x;        // 0..255 (channel pair)
    const int chunk = blockIdx.y;
    const int b     = blockIdx.z;

    const size_t base = ((size_t)b * T_LEN + (size_t)chunk * CLEN) * D_HALF2 + c2;
    const __half2* pf  = g_f  + base;
    const __half2* pxt = g_xt + base;

    float2 P = make_float2(1.0f, 1.0f);
    float2 C = make_float2(0.0f, 0.0f);
    #pragma unroll 5
    for (int t = 0; t < CLEN; t++) {
        const size_t off = (size_t)t * D_HALF2;
        const float2 f  = __half22float2(pf [off]);
        const float2 xt = __half22float2(pxt[off]);
        C.x = fmaf(f.x, C.x, (1.0f - f.x) * xt.x);
        C.y = fmaf(f.y, C.y, (1.0f - f.y) * xt.y);
        P.x *= f.x;
        P.y *= f.y;
    }
    const size_t sidx = ((size_t)b * NCHUNK + chunk) * (D_FULL / 2) + c2;
    *(float2*)&g_P[2 * sidx] = P;
    *(float2*)&g_C[2 * sidx] = C;
}

// ---------------------------------------------------------------------------
// Scan phase 2: serial scan over chunk summaries -> carry-in per chunk.
// ---------------------------------------------------------------------------
__global__ __launch_bounds__(256)
void scan_phase2(void)
{
    const int idx = blockIdx.x * 256 + threadIdx.x;   // 0..16383
    const int b = idx >> 9;
    const int c = idx & (D_FULL - 1);

    float carry = 0.0f;
    #pragma unroll
    for (int k = 0; k < NCHUNK; k++) {
        const size_t sidx = ((size_t)b * NCHUNK + k) * D_FULL + c;
        g_cin[sidx] = carry;
        carry = fmaf(g_P[sidx], carry, g_C[sidx]);
    }
}

// ---------------------------------------------------------------------------
// Scan phase 3: recurrence from carry-in; fused highway output (float2).
// ---------------------------------------------------------------------------
__global__ __launch_bounds__(256)
void scan_phase3(const float* __restrict__ x, float* __restrict__ out)
{
    const int c2    = threadIdx.x;
    const int chunk = blockIdx.y;
    const int b     = blockIdx.z;

    const size_t base = ((size_t)b * T_LEN + (size_t)chunk * CLEN) * D_HALF2 + c2;
    const __half2* pf  = g_f  + base;
    const __half2* pxt = g_xt + base;
    const __half2* pr  = g_r  + base;
    const float2*  px  = (const float2*)x   + base;
    float2*        po  = (float2*)out        + base;

    float2 cacc = *(const float2*)&g_cin[2 * (((size_t)b * NCHUNK + chunk) * (D_FULL / 2) + c2)];

    #pragma unroll 5
    for (int t = 0; t < CLEN; t++) {
        const size_t off = (size_t)t * D_HALF2;
        const float2 f  = __half22float2(pf [off]);
        const float2 xt = __half22float2(pxt[off]);
        const float2 r  = __half22float2(pr [off]);
        const float2 xv = px[off];
        cacc.x = fmaf(f.x, cacc.x, (1.0f - f.x) * xt.x);
        cacc.y = fmaf(f.y, cacc.y, (1.0f - f.y) * xt.y);
        float2 h;
        h.x = fmaf(r.x, cacc.x, (1.0f - r.x) * xv.x);
        h.y = fmaf(r.y, cacc.y, (1.0f - r.y) * xv.y);
        po[off] = h;
    }
}

// ---------------------------------------------------------------------------
extern "C" void kernel_launch(void* const* d_in, const int* in_sizes, int n_in,
                              void* d_out, int out_size)
{
    const float* x   = (const float*)d_in[0];
    const float* W1  = (const float*)d_in[1];
    const float* bf1 = (const float*)d_in[2];
    const float* br1 = (const float*)d_in[3];
    const float* W2  = (const float*)d_in[4];
    const float* bf2 = (const float*)d_in[5];
    const float* br2 = (const float*)d_in[6];
    float* out = (float*)d_out;

    (void)n_in; (void)in_sizes; (void)out_size;

    dim3 cxgrid(NKT, NMBLK, 2);                // (16, 500, 2)
    convert_x_kernel<<<cxgrid, 256>>>(x);
    dim3 cwgrid(NKT, 6, 2);                    // (16, 6, 2)
    convert_w_kernel<<<cwgrid, 256>>>(W1, W2);

    dim3 ggrid(12, NMBLK);                     // (12, 500)
    gemm_mma_kernel<<<ggrid, 256>>>(bf1, br1, bf2, br2);

    dim3 sgrid(1, NCHUNK, B_SZ);               // (1, 40, 32)
    scan_phase1<<<sgrid, 256>>>();
    scan_phase2<<<(B_SZ * D_FULL) / 256, 256>>>();
    scan_phase3<<<sgrid, 256>>>(x, out);
}

// round 12
// speedup vs baseline: 2.0196x; 1.0849x over previous
#include <cuda_runtime.h>
#include <cuda_fp16.h>
#include <cstdint>
#include <math.h>

// Shapes (fixed): B=32, T=2000, D=512, halves of 256, 3H=768.
#define M_TOTAL   64000
#define B_SZ      32
#define T_LEN     2000
#define D_FULL    512
#define D_HALF    256
#define D_HALF2   256            // D_FULL in half2 units
#define N_COLS    768

// Scan chunking
#define NCHUNK 40
#define CLEN   50

// GEMM tiling (mma.sync m16n8k16 fp16)
#define BM 128
#define BN 128
#define BK 16
#define NKT (D_HALF / BK)        // 16 k-tiles
#define NST (NKT / 2)            // 8 supertiles (BK=32 staging)
#define NMBLK (M_TOTAL / BM)     // 500
#define TILE_U32 1024            // 128 x 16 fp16 = 4KB
#define STILE_U32 (2 * TILE_U32) // supertile = 8KB

// Scratch (device globals: allocation-free per harness rules).
__device__ __half2 g_xt[M_TOTAL * D_HALF2];
__device__ __half2 g_f [M_TOTAL * D_HALF2];
__device__ __half2 g_r [M_TOTAL * D_HALF2];
__device__ float g_P[B_SZ * NCHUNK * D_FULL];
__device__ float g_C[B_SZ * NCHUNK * D_FULL];
// pre-converted fp16 operand images in fragment-packed SMEM tile layout
__device__ uint32_t g_xc[2 * NMBLK * NKT * TILE_U32];   // 65.5 MB
__device__ uint32_t g_wc[2 * 6 * NKT * TILE_U32];       // 0.8 MB

__device__ __forceinline__ float sigmoidf_(float v) {
    return 1.0f / (1.0f + __expf(-v));
}

__device__ __forceinline__ uint32_t smem_u32(const void* p) {
    uint32_t a;
    asm("{ .reg .u64 t; cvta.to.shared.u64 t, %1; cvt.u32.u64 %0, t; }"
        : "=r"(a) : "l"(p));
    return a;
}

__device__ __forceinline__ uint32_t pack_h2(float lo, float hi) {
    __half2 h = __halves2half2(__float2half_rn(lo), __float2half_rn(hi));
    return *(uint32_t*)&h;
}

__device__ __forceinline__ void cp_async16(uint32_t smem_dst, const void* gptr) {
    asm volatile("cp.async.ca.shared.global [%0], [%1], 16;"
                 :: "r"(smem_dst), "l"(gptr) : "memory");
}
__device__ __forceinline__ void cp_async_commit() {
    asm volatile("cp.async.commit_group;" ::: "memory");
}
template <int N>
__device__ __forceinline__ void cp_async_wait() {
    asm volatile("cp.async.wait_group %0;" :: "n"(N) : "memory");
}

__device__ __forceinline__ void mma_f16(float* c, uint32_t a0, uint32_t a1,
                                        uint32_t a2, uint32_t a3,
                                        uint32_t b0, uint32_t b1) {
    asm volatile(
        "mma.sync.aligned.m16n8k16.row.col.f32.f16.f16.f32 "
        "{%0,%1,%2,%3}, {%4,%5,%6,%7}, {%8,%9}, {%0,%1,%2,%3};"
        : "+f"(c[0]), "+f"(c[1]), "+f"(c[2]), "+f"(c[3])
        : "r"(a0), "r"(a1), "r"(a2), "r"(a3), "r"(b0), "r"(b1));
}

// Fragment-packed layouts (validated R8/R9):
__device__ __forceinline__ int a_off(int r, int p) {
    return ((r >> 4) << 7) + ((r & 7) << 4) + ((p & 3) << 2)
         + (((r >> 3) & 1) << 1) + (p >> 2);
}
__device__ __forceinline__ int b_off(int n, int p) {
    return (n << 3) + ((p & 3) << 1) + (p >> 2);
}

// ---------------------------------------------------------------------------
// Fused pre-pass: y<500 converts x tiles; y>=500 converts W tiles (nblk=y-500).
// ---------------------------------------------------------------------------
__global__ __launch_bounds__(256)
void convert_kernel(const float* __restrict__ x,
                    const float* __restrict__ W1, const float* __restrict__ W2)
{
    const int kt  = blockIdx.x;
    const int s   = blockIdx.z;
    const int tid = threadIdx.x;

    if (blockIdx.y < NMBLK) {
        const int mblk = blockIdx.y;
        uint32_t* dst = g_xc + ((size_t)((s * NMBLK + mblk) * NKT + kt)) * TILE_U32;
        const float* src = x + (size_t)(mblk * BM) * D_FULL + s * D_HALF + kt * BK;
        #pragma unroll
        for (int j = 0; j < 2; j++) {
            const int idx = tid + 256 * j;        // 0..511
            const int row = idx >> 2;
            const int c4  = idx & 3;
            float4 v = *(const float4*)(src + (size_t)row * D_FULL + 4 * c4);
            dst[a_off(row, 2 * c4)]     = pack_h2(v.x, v.y);
            dst[a_off(row, 2 * c4 + 1)] = pack_h2(v.z, v.w);
        }
    } else {
        const int nblk = blockIdx.y - NMBLK;      // 0..5
        const float* W = s ? W2 : W1;
        uint32_t* dst = g_wc + ((size_t)((s * 6 + nblk) * NKT + kt)) * TILE_U32;
        const float* src = W + (size_t)(kt * BK) * N_COLS + nblk * BN;
        #pragma unroll
        for (int j = 0; j < 4; j++) {
            const int idx = tid + 256 * j;        // p*128 + n
            const int p = idx >> 7;
            const int n = idx & 127;
            const float w0 = src[(size_t)(2 * p)     * N_COLS + n];
            const float w1 = src[(size_t)(2 * p + 1) * N_COLS + n];
            dst[b_off(n, p)] = pack_h2(w0, w1);
        }
    }
}

// ---------------------------------------------------------------------------
// Kernel 1: fp16 mma.sync (m16n8k16) GEMM. (unchanged from R10)
// ---------------------------------------------------------------------------
__global__ __launch_bounds__(256, 2)
void gemm_mma_kernel(const float* __restrict__ bf1, const float* __restrict__ br1,
                     const float* __restrict__ bf2, const float* __restrict__ br2)
{
    const int s    = blockIdx.x / 6;
    const int nblk = blockIdx.x % 6;
    const int mblk = blockIdx.y;

    const float* bf = s ? bf2 : bf1;
    const float* br = s ? br2 : br1;

    __shared__ uint32_t sA[3][STILE_U32];  // 3 x 8KB
    __shared__ uint32_t sB[3][STILE_U32];  // 3 x 8KB

    const int tid    = threadIdx.x;
    const int wid    = tid >> 5;
    const int lid    = tid & 31;
    const int gid    = lid >> 2;
    const int tig    = lid & 3;
    const int warp_m = wid >> 2;
    const int warp_n = wid & 3;

    const uint32_t* Asrc = g_xc + ((size_t)(s * NMBLK + mblk)) * NKT * TILE_U32;
    const uint32_t* Bsrc = g_wc + ((size_t)(s * 6 + nblk)) * NKT * TILE_U32;

    auto prefetch = [&](int st) {
        const int buf = st % 3;
        const int e0 = tid * 4;
        const int e1 = tid * 4 + TILE_U32;
        const uint32_t* ga = Asrc + (size_t)st * STILE_U32;
        const uint32_t* gb = Bsrc + (size_t)st * STILE_U32;
        cp_async16(smem_u32(&sA[buf][e0]), ga + e0);
        cp_async16(smem_u32(&sA[buf][e1]), ga + e1);
        cp_async16(smem_u32(&sB[buf][e0]), gb + e0);
        cp_async16(smem_u32(&sB[buf][e1]), gb + e1);
        cp_async_commit();
    };

    float acc[4][4][4];
    #pragma unroll
    for (int mi = 0; mi < 4; mi++)
        #pragma unroll
        for (int ni = 0; ni < 4; ni++)
            #pragma unroll
            for (int q = 0; q < 4; q++) acc[mi][ni][q] = 0.0f;

    prefetch(0);
    prefetch(1);

    #pragma unroll 1
    for (int st = 0; st < NST; st++) {
        if (st + 1 < NST) cp_async_wait<1>();
        else              cp_async_wait<0>();
        __syncthreads();
        if (st + 2 < NST) prefetch(st + 2);

        #pragma unroll
        for (int sub = 0; sub < 2; sub++) {
            const uint32_t* A  = &sA[st % 3][sub * TILE_U32];
            const uint32_t* Bs = &sB[st % 3][sub * TILE_U32];

            uint4 afr[4];
            #pragma unroll
            for (int mi = 0; mi < 4; mi++)
                afr[mi] = *(const uint4*)&A[(warp_m * 4 + mi) * 128 + gid * 16 + tig * 4];

            #pragma unroll
            for (int ni = 0; ni < 4; ni++) {
                const int n = warp_n * 32 + ni * 8 + gid;
                const uint2 bv = *(const uint2*)&Bs[n * 8 + tig * 2];
                #pragma unroll
                for (int mi = 0; mi < 4; mi++)
                    mma_f16(acc[mi][ni], afr[mi].x, afr[mi].z, afr[mi].y, afr[mi].w,
                            bv.x, bv.y);
            }
        }
    }

    // ---- epilogue: fused bias + sigmoid, half2 stores ----
    const int n0      = nblk * BN;
    const int region  = n0 >> 8;
    __half2* dst      = (region == 0) ? g_xt : ((region == 1) ? g_f : g_r);
    const float* bias = (region == 1) ? bf : br;

    #pragma unroll
    for (int mi = 0; mi < 4; mi++) {
        const int row0 = mblk * BM + warp_m * 64 + mi * 16 + gid;
        #pragma unroll
        for (int ni = 0; ni < 4; ni++) {
            const int h = (n0 & (D_HALF - 1)) + warp_n * 32 + ni * 8 + 2 * tig;
            float v0 = acc[mi][ni][0], v1 = acc[mi][ni][1];
            float v2 = acc[mi][ni][2], v3 = acc[mi][ni][3];
            if (region != 0) {
                const float b0 = __ldg(bias + h), b1 = __ldg(bias + h + 1);
                v0 = sigmoidf_(v0 + b0);
                v1 = sigmoidf_(v1 + b1);
                v2 = sigmoidf_(v2 + b0);
                v3 = sigmoidf_(v3 + b1);
            }
            const size_t cp = (size_t)(s * D_HALF + h) >> 1;
            dst[(size_t)row0 * D_HALF2 + cp]       = __floats2half2_rn(v0, v1);
            dst[(size_t)(row0 + 8) * D_HALF2 + cp] = __floats2half2_rn(v2, v3);
        }
    }
}

// ---------------------------------------------------------------------------
// Scan phase 1: 128 threads, 4 channels/thread (2x half2); float4 summaries.
// Grid (1, NCHUNK, B_SZ).
// ---------------------------------------------------------------------------
__global__ __launch_bounds__(128)
void scan_phase1(void)
{
    const int c4    = threadIdx.x;        // 0..127 (channel quad)
    const int chunk = blockIdx.y;
    const int b     = blockIdx.z;

    const size_t base = ((size_t)b * T_LEN + (size_t)chunk * CLEN) * D_HALF2 + 2 * c4;
    const __half2* pf  = g_f  + base;
    const __half2* pxt = g_xt + base;

    float4 P = make_float4(1.0f, 1.0f, 1.0f, 1.0f);
    float4 C = make_float4(0.0f, 0.0f, 0.0f, 0.0f);
    #pragma unroll 5
    for (int t = 0; t < CLEN; t++) {
        const size_t off = (size_t)t * D_HALF2;
        const __half2 fa = pf[off],  fb = pf[off + 1];
        const __half2 xa = pxt[off], xb = pxt[off + 1];
        const float2 f0 = __half22float2(fa), f1 = __half22float2(fb);
        const float2 x0 = __half22float2(xa), x1 = __half22float2(xb);
        C.x = fmaf(f0.x, C.x, (1.0f - f0.x) * x0.x);
        C.y = fmaf(f0.y, C.y, (1.0f - f0.y) * x0.y);
        C.z = fmaf(f1.x, C.z, (1.0f - f1.x) * x1.x);
        C.w = fmaf(f1.y, C.w, (1.0f - f1.y) * x1.y);
        P.x *= f0.x;  P.y *= f0.y;  P.z *= f1.x;  P.w *= f1.y;
    }
    const size_t sidx = ((size_t)b * NCHUNK + chunk) * D_FULL + 4 * c4;
    *(float4*)&g_P[sidx] = P;
    *(float4*)&g_C[sidx] = C;
}

// ---------------------------------------------------------------------------
// Scan phase 3: computes its own carry-in from g_P/g_C (L2-resident, 5.2MB),
// then recurrence + fused highway output. 128 threads, 4 channels/thread.
// ---------------------------------------------------------------------------
__global__ __launch_bounds__(128)
void scan_phase3(const float* __restrict__ x, float* __restrict__ out)
{
    const int c4    = threadIdx.x;        // 0..127
    const int chunk = blockIdx.y;
    const int b     = blockIdx.z;

    // ---- local carry-in scan over preceding chunk summaries ----
    float4 cacc = make_float4(0.0f, 0.0f, 0.0f, 0.0f);
    for (int k = 0; k < chunk; k++) {
        const size_t sidx = ((size_t)b * NCHUNK + k) * D_FULL + 4 * c4;
        const float4 Pv = *(const float4*)&g_P[sidx];
        const float4 Cv = *(const float4*)&g_C[sidx];
        cacc.x = fmaf(Pv.x, cacc.x, Cv.x);
        cacc.y = fmaf(Pv.y, cacc.y, Cv.y);
        cacc.z = fmaf(Pv.z, cacc.z, Cv.z);
        cacc.w = fmaf(Pv.w, cacc.w, Cv.w);
    }

    const size_t base = ((size_t)b * T_LEN + (size_t)chunk * CLEN) * D_HALF2 + 2 * c4;
    const __half2* pf  = g_f  + base;
    const __half2* pxt = g_xt + base;
    const __half2* pr  = g_r  + base;
    const float*   px  = x   + 2 * base;    // float index = 2 * half2 index
    float*         po  = out + 2 * base;

    #pragma unroll 5
    for (int t = 0; t < CLEN; t++) {
        const size_t off = (size_t)t * D_HALF2;
        const float2 f0 = __half22float2(pf[off]),  f1 = __half22float2(pf[off + 1]);
        const float2 t0 = __half22float2(pxt[off]), t1 = __half22float2(pxt[off + 1]);
        const float2 r0 = __half22float2(pr[off]),  r1 = __half22float2(pr[off + 1]);
        const float4 xv = *(const float4*)(px + 2 * off);
        cacc.x = fmaf(f0.x, cacc.x, (1.0f - f0.x) * t0.x);
        cacc.y = fmaf(f0.y, cacc.y, (1.0f - f0.y) * t0.y);
        cacc.z = fmaf(f1.x, cacc.z, (1.0f - f1.x) * t1.x);
        cacc.w = fmaf(f1.y, cacc.w, (1.0f - f1.y) * t1.y);
        float4 h;
        h.x = fmaf(r0.x, cacc.x, (1.0f - r0.x) * xv.x);
        h.y = fmaf(r0.y, cacc.y, (1.0f - r0.y) * xv.y);
        h.z = fmaf(r1.x, cacc.z, (1.0f - r1.x) * xv.z);
        h.w = fmaf(r1.y, cacc.w, (1.0f - r1.y) * xv.w);
        *(float4*)(po + 2 * off) = h;
    }
}

// ---------------------------------------------------------------------------
extern "C" void kernel_launch(void* const* d_in, const int* in_sizes, int n_in,
                              void* d_out, int out_size)
{
    const float* x   = (const float*)d_in[0];
    const float* W1  = (const float*)d_in[1];
    const float* bf1 = (const float*)d_in[2];
    const float* br1 = (const float*)d_in[3];
    const float* W2  = (const float*)d_in[4];
    const float* bf2 = (const float*)d_in[5];
    const float* br2 = (const float*)d_in[6];
    float* out = (float*)d_out;

    (void)n_in; (void)in_sizes; (void)out_size;

    dim3 cgrid(NKT, NMBLK + 6, 2);             // (16, 506, 2) fused convert
    convert_kernel<<<cgrid, 256>>>(x, W1, W2);

    dim3 ggrid(12, NMBLK);                     // (12, 500)
    gemm_mma_kernel<<<ggrid, 256>>>(bf1, br1, bf2, br2);

    dim3 sgrid(1, NCHUNK, B_SZ);               // (1, 40, 32)
    scan_phase1<<<sgrid, 128>>>();
    scan_phase3<<<sgrid, 128>>>(x, out);
}

// round 15
// speedup vs baseline: 2.0441x; 1.0121x over previous
#include <cuda_runtime.h>
#include <cuda_fp16.h>
#include <cstdint>
#include <math.h>

// Shapes (fixed): B=32, T=2000, D=512, halves of 256, 3H=768.
#define M_TOTAL   64000
#define B_SZ      32
#define T_LEN     2000
#define D_FULL    512
#define D_HALF    256
#define D_HALF2   256            // D_FULL in half2 units
#define N_COLS    768

// Scan chunking
#define NCHUNK 40
#define CLEN   50

// GEMM tiling (mma.sync m16n8k16 fp16)
#define BM 128
#define BN 128
#define BK 16
#define NKT (D_HALF / BK)        // 16 k-tiles
#define NST (NKT / 2)            // 8 supertiles (BK=32 staging)
#define NMBLK (M_TOTAL / BM)     // 500
#define TILE_U32 1024            // 128 x 16 fp16 = 4KB
#define STILE_U32 (2 * TILE_U32) // supertile = 8KB

// Scratch (device globals: allocation-free per harness rules).
__device__ __half2 g_xt[M_TOTAL * D_HALF2];
__device__ __half2 g_f [M_TOTAL * D_HALF2];
__device__ __half2 g_r [M_TOTAL * D_HALF2];
__device__ float g_P[B_SZ * NCHUNK * D_FULL];
__device__ float g_C[B_SZ * NCHUNK * D_FULL];
// pre-converted fp16 operand images in fragment-packed SMEM tile layout
__device__ uint32_t g_xc[2 * NMBLK * NKT * TILE_U32];   // 65.5 MB
__device__ uint32_t g_wc[2 * 6 * NKT * TILE_U32];       // 0.8 MB

__device__ __forceinline__ float sigmoidf_(float v) {
    return 1.0f / (1.0f + __expf(-v));
}

__device__ __forceinline__ uint32_t smem_u32(const void* p) {
    uint32_t a;
    asm("{ .reg .u64 t; cvta.to.shared.u64 t, %1; cvt.u32.u64 %0, t; }"
        : "=r"(a) : "l"(p));
    return a;
}

__device__ __forceinline__ uint32_t pack_h2(float lo, float hi) {
    __half2 h = __halves2half2(__float2half_rn(lo), __float2half_rn(hi));
    return *(uint32_t*)&h;
}

__device__ __forceinline__ void cp_async16(uint32_t smem_dst, const void* gptr) {
    asm volatile("cp.async.ca.shared.global [%0], [%1], 16;"
                 :: "r"(smem_dst), "l"(gptr) : "memory");
}
__device__ __forceinline__ void cp_async_commit() {
    asm volatile("cp.async.commit_group;" ::: "memory");
}
template <int N>
__device__ __forceinline__ void cp_async_wait() {
    asm volatile("cp.async.wait_group %0;" :: "n"(N) : "memory");
}

__device__ __forceinline__ void mma_f16(float* c, uint32_t a0, uint32_t a1,
                                        uint32_t a2, uint32_t a3,
                                        uint32_t b0, uint32_t b1) {
    asm volatile(
        "mma.sync.aligned.m16n8k16.row.col.f32.f16.f16.f32 "
        "{%0,%1,%2,%3}, {%4,%5,%6,%7}, {%8,%9}, {%0,%1,%2,%3};"
        : "+f"(c[0]), "+f"(c[1]), "+f"(c[2]), "+f"(c[3])
        : "r"(a0), "r"(a1), "r"(a2), "r"(a3), "r"(b0), "r"(b1));
}

// Fragment-packed layouts (validated R8/R9): NO row-dependent swizzle.
// uint32 at a_off(r,p) holds fp16 pair (channels 2p, 2p+1) of row r.
__device__ __forceinline__ int a_off(int r, int p) {
    return ((r >> 4) << 7) + ((r & 7) << 4) + ((p & 3) << 2)
         + (((r >> 3) & 1) << 1) + (p >> 2);
}
__device__ __forceinline__ int b_off(int n, int p) {
    return (n << 3) + ((p & 3) << 1) + (p >> 2);
}

// ---------------------------------------------------------------------------
// Fused pre-pass: y<500 converts x tiles; y>=500 converts W tiles (nblk=y-500).
// ---------------------------------------------------------------------------
__global__ __launch_bounds__(256)
void convert_kernel(const float* __restrict__ x,
                    const float* __restrict__ W1, const float* __restrict__ W2)
{
    const int kt  = blockIdx.x;
    const int s   = blockIdx.z;
    const int tid = threadIdx.x;

    if (blockIdx.y < NMBLK) {
        const int mblk = blockIdx.y;
        uint32_t* dst = g_xc + ((size_t)((s * NMBLK + mblk) * NKT + kt)) * TILE_U32;
        const float* src = x + (size_t)(mblk * BM) * D_FULL + s * D_HALF + kt * BK;
        #pragma unroll
        for (int j = 0; j < 2; j++) {
            const int idx = tid + 256 * j;        // 0..511
            const int row = idx >> 2;
            const int c4  = idx & 3;
            float4 v = *(const float4*)(src + (size_t)row * D_FULL + 4 * c4);
            dst[a_off(row, 2 * c4)]     = pack_h2(v.x, v.y);
            dst[a_off(row, 2 * c4 + 1)] = pack_h2(v.z, v.w);
        }
    } else {
        const int nblk = blockIdx.y - NMBLK;      // 0..5
        const float* W = s ? W2 : W1;
        uint32_t* dst = g_wc + ((size_t)((s * 6 + nblk) * NKT + kt)) * TILE_U32;
        const float* src = W + (size_t)(kt * BK) * N_COLS + nblk * BN;
        #pragma unroll
        for (int j = 0; j < 4; j++) {
            const int idx = tid + 256 * j;        // p*128 + n
            const int p = idx >> 7;
            const int n = idx & 127;
            const float w0 = src[(size_t)(2 * p)     * N_COLS + n];
            const float w1 = src[(size_t)(2 * p + 1) * N_COLS + n];
            dst[b_off(n, p)] = pack_h2(w0, w1);
        }
    }
}

// ---------------------------------------------------------------------------
// Kernel 1: fp16 mma.sync (m16n8k16) GEMM.
// 3-stage supertile cp.async pipeline (48KB static smem, known-good R10/R11).
// ---------------------------------------------------------------------------
__global__ __launch_bounds__(256, 2)
void gemm_mma_kernel(const float* __restrict__ bf1, const float* __restrict__ br1,
                     const float* __restrict__ bf2, const float* __restrict__ br2)
{
    const int s    = blockIdx.x / 6;
    const int nblk = blockIdx.x % 6;
    const int mblk = blockIdx.y;

    const float* bf = s ? bf2 : bf1;
    const float* br = s ? br2 : br1;

    __shared__ uint32_t sA[3][STILE_U32];  // 3 x 8KB
    __shared__ uint32_t sB[3][STILE_U32];  // 3 x 8KB

    const int tid    = threadIdx.x;
    const int wid    = tid >> 5;
    const int lid    = tid & 31;
    const int gid    = lid >> 2;
    const int tig    = lid & 3;
    const int warp_m = wid >> 2;
    const int warp_n = wid & 3;

    const uint32_t* Asrc = g_xc + ((size_t)(s * NMBLK + mblk)) * NKT * TILE_U32;
    const uint32_t* Bsrc = g_wc + ((size_t)(s * 6 + nblk)) * NKT * TILE_U32;

    auto prefetch = [&](int st) {
        const int buf = st % 3;
        const int e0 = tid * 4;
        const int e1 = tid * 4 + TILE_U32;
        const uint32_t* ga = Asrc + (size_t)st * STILE_U32;
        const uint32_t* gb = Bsrc + (size_t)st * STILE_U32;
        cp_async16(smem_u32(&sA[buf][e0]), ga + e0);
        cp_async16(smem_u32(&sA[buf][e1]), ga + e1);
        cp_async16(smem_u32(&sB[buf][e0]), gb + e0);
        cp_async16(smem_u32(&sB[buf][e1]), gb + e1);
        cp_async_commit();
    };

    float acc[4][4][4];
    #pragma unroll
    for (int mi = 0; mi < 4; mi++)
        #pragma unroll
        for (int ni = 0; ni < 4; ni++)
            #pragma unroll
            for (int q = 0; q < 4; q++) acc[mi][ni][q] = 0.0f;

    prefetch(0);
    prefetch(1);

    #pragma unroll 1
    for (int st = 0; st < NST; st++) {
        // tail (R6 lesson): on the final iteration the newest committed group
        // is supertile NST-1 itself — drain fully.
        if (st + 1 < NST) cp_async_wait<1>();
        else              cp_async_wait<0>();
        __syncthreads();   // tile st resident; all threads done with st-1
        if (st + 2 < NST) prefetch(st + 2);   // refills buf (st-1)%3: safe

        #pragma unroll
        for (int sub = 0; sub < 2; sub++) {
            const uint32_t* A  = &sA[st % 3][sub * TILE_U32];
            const uint32_t* Bs = &sB[st % 3][sub * TILE_U32];

            uint4 afr[4];
            #pragma unroll
            for (int mi = 0; mi < 4; mi++)
                afr[mi] = *(const uint4*)&A[(warp_m * 4 + mi) * 128 + gid * 16 + tig * 4];

            #pragma unroll
            for (int ni = 0; ni < 4; ni++) {
                const int n = warp_n * 32 + ni * 8 + gid;
                const uint2 bv = *(const uint2*)&Bs[n * 8 + tig * 2];
                #pragma unroll
                for (int mi = 0; mi < 4; mi++)
                    mma_f16(acc[mi][ni], afr[mi].x, afr[mi].z, afr[mi].y, afr[mi].w,
                            bv.x, bv.y);
            }
        }
    }

    // ---- epilogue: fused bias + sigmoid, half2 stores ----
    const int n0      = nblk * BN;
    const int region  = n0 >> 8;
    __half2* dst      = (region == 0) ? g_xt : ((region == 1) ? g_f : g_r);
    const float* bias = (region == 1) ? bf : br;

    #pragma unroll
    for (int mi = 0; mi < 4; mi++) {
        const int row0 = mblk * BM + warp_m * 64 + mi * 16 + gid;
        #pragma unroll
        for (int ni = 0; ni < 4; ni++) {
            const int h = (n0 & (D_HALF - 1)) + warp_n * 32 + ni * 8 + 2 * tig;
            float v0 = acc[mi][ni][0], v1 = acc[mi][ni][1];
            float v2 = acc[mi][ni][2], v3 = acc[mi][ni][3];
            if (region != 0) {
                const float b0 = __ldg(bias + h), b1 = __ldg(bias + h + 1);
                v0 = sigmoidf_(v0 + b0);
                v1 = sigmoidf_(v1 + b1);
                v2 = sigmoidf_(v2 + b0);
                v3 = sigmoidf_(v3 + b1);
            }
            const size_t cp = (size_t)(s * D_HALF + h) >> 1;
            dst[(size_t)row0 * D_HALF2 + cp]       = __floats2half2_rn(v0, v1);
            dst[(size_t)(row0 + 8) * D_HALF2 + cp] = __floats2half2_rn(v2, v3);
        }
    }
}

// ---------------------------------------------------------------------------
// Scan phase 1: 128 threads, 4 channels/thread (2x half2); float4 summaries.
// ---------------------------------------------------------------------------
__global__ __launch_bounds__(128)
void scan_phase1(void)
{
    const int c4    = threadIdx.x;        // 0..127 (channel quad)
    const int chunk = blockIdx.y;
    const int b     = blockIdx.z;

    const size_t base = ((size_t)b * T_LEN + (size_t)chunk * CLEN) * D_HALF2 + 2 * c4;
    const __half2* pf  = g_f  + base;
    const __half2* pxt = g_xt + base;

    float4 P = make_float4(1.0f, 1.0f, 1.0f, 1.0f);
    float4 C = make_float4(0.0f, 0.0f, 0.0f, 0.0f);
    #pragma unroll 5
    for (int t = 0; t < CLEN; t++) {
        const size_t off = (size_t)t * D_HALF2;
        const float2 f0 = __half22float2(pf[off]),  f1 = __half22float2(pf[off + 1]);
        const float2 x0 = __half22float2(pxt[off]), x1 = __half22float2(pxt[off + 1]);
        C.x = fmaf(f0.x, C.x, (1.0f - f0.x) * x0.x);
        C.y = fmaf(f0.y, C.y, (1.0f - f0.y) * x0.y);
        C.z = fmaf(f1.x, C.z, (1.0f - f1.x) * x1.x);
        C.w = fmaf(f1.y, C.w, (1.0f - f1.y) * x1.y);
        P.x *= f0.x;  P.y *= f0.y;  P.z *= f1.x;  P.w *= f1.y;
    }
    const size_t sidx = ((size_t)b * NCHUNK + chunk) * D_FULL + 4 * c4;
    *(float4*)&g_P[sidx] = P;
    *(float4*)&g_C[sidx] = C;
}

// ---------------------------------------------------------------------------
// Scan phase 3: local carry-in from g_P/g_C (L2-resident), recurrence +
// highway. x read from the fp16 image g_xc. R13 BUG FIXED: the R8 layout has
// no row-XOR swizzle — index is a_off(rr, p) directly.
// 128 threads, 4 channels/thread.
// ---------------------------------------------------------------------------
__global__ __launch_bounds__(128)
void scan_phase3(float* __restrict__ out)
{
    const int c4    = threadIdx.x;        // 0..127
    const int chunk = blockIdx.y;
    const int b     = blockIdx.z;

    // ---- carry-in scan over preceding chunk summaries ----
    float4 cacc = make_float4(0.0f, 0.0f, 0.0f, 0.0f);
    for (int k = 0; k < chunk; k++) {
        const size_t sidx = ((size_t)b * NCHUNK + k) * D_FULL + 4 * c4;
        const float4 Pv = *(const float4*)&g_P[sidx];
        const float4 Cv = *(const float4*)&g_C[sidx];
        cacc.x = fmaf(Pv.x, cacc.x, Cv.x);
        cacc.y = fmaf(Pv.y, cacc.y, Cv.y);
        cacc.z = fmaf(Pv.z, cacc.z, Cv.z);
        cacc.w = fmaf(Pv.w, cacc.w, Cv.w);
    }

    const size_t base = ((size_t)b * T_LEN + (size_t)chunk * CLEN) * D_HALF2 + 2 * c4;
    const __half2* pf  = g_f  + base;
    const __half2* pxt = g_xt + base;
    const __half2* pr  = g_r  + base;
    float*         po  = out + 2 * base;

    // ---- x image addressing: channels c..c+3, c = 4*c4 ----
    const int c   = 4 * c4;
    const int s   = c >> 8;                 // half
    const int kt  = (c >> 4) & 15;          // k-tile within half
    const int p0  = (c & 15) >> 1;          // even pair index {0,2,4,6}
    // a_off k-part for p0 and p0+1: 4*(p0&3) + (p0>>2) and 4*((p0&3)+1) + (p0>>2)
    const int koff0 = 4 * (p0 & 3) + (p0 >> 2);
    const int koff1 = koff0 + 4;            // (p0+1)&3 = (p0&3)+1, same >>2 bit
    const uint32_t* img_half = g_xc + (size_t)s * NMBLK * NKT * TILE_U32
                                    + (size_t)kt * TILE_U32;
    const int m0 = b * T_LEN + chunk * CLEN;

    #pragma unroll 2
    for (int t = 0; t < CLEN; t++) {
        const size_t off = (size_t)t * D_HALF2;
        const float2 f0 = __half22float2(pf[off]),  f1 = __half22float2(pf[off + 1]);
        const float2 t0 = __half22float2(pxt[off]), t1 = __half22float2(pxt[off + 1]);
        const float2 r0 = __half22float2(pr[off]),  r1 = __half22float2(pr[off + 1]);

        // x from fp16 image: row m -> tile m>>7, in-tile row rr = m&127
        const int m  = m0 + t;
        const int rr = m & 127;
        const uint32_t* tb = img_half + (size_t)(m >> 7) * (NKT * TILE_U32);
        const int rbase = ((rr >> 4) << 7) + ((rr & 7) << 4) + (((rr >> 3) & 1) << 1);
        const uint32_t w0 = tb[rbase + koff0];          // ch c, c+1
        const uint32_t w1 = tb[rbase + koff1];          // ch c+2, c+3
        const float2 xv0 = __half22float2(*(const __half2*)&w0);
        const float2 xv1 = __half22float2(*(const __half2*)&w1);

        cacc.x = fmaf(f0.x, cacc.x, (1.0f - f0.x) * t0.x);
        cacc.y = fmaf(f0.y, cacc.y, (1.0f - f0.y) * t0.y);
        cacc.z = fmaf(f1.x, cacc.z, (1.0f - f1.x) * t1.x);
        cacc.w = fmaf(f1.y, cacc.w, (1.0f - f1.y) * t1.y);
        float4 h;
        h.x = fmaf(r0.x, cacc.x, (1.0f - r0.x) * xv0.x);
        h.y = fmaf(r0.y, cacc.y, (1.0f - r0.y) * xv0.y);
        h.z = fmaf(r1.x, cacc.z, (1.0f - r1.x) * xv1.x);
        h.w = fmaf(r1.y, cacc.w, (1.0f - r1.y) * xv1.y);
        *(float4*)(po + 2 * off) = h;
    }
}

// ---------------------------------------------------------------------------
extern "C" void kernel_launch(void* const* d_in, const int* in_sizes, int n_in,
                              void* d_out, int out_size)
{
    const float* x   = (const float*)d_in[0];
    const float* W1  = (const float*)d_in[1];
    const float* bf1 = (const float*)d_in[2];
    const float* br1 = (const float*)d_in[3];
    const float* W2  = (const float*)d_in[4];
    const float* bf2 = (const float*)d_in[5];
    const float* br2 = (const float*)d_in[6];
    float* out = (float*)d_out;

    (void)n_in; (void)in_sizes; (void)out_size;

    dim3 cgrid(NKT, NMBLK + 6, 2);             // (16, 506, 2) fused convert
    convert_kernel<<<cgrid, 256>>>(x, W1, W2);

    dim3 ggrid(12, NMBLK);                     // (12, 500)
    gemm_mma_kernel<<<ggrid, 256>>>(bf1, br1, bf2, br2);

    dim3 sgrid(1, NCHUNK, B_SZ);               // (1, 40, 32)
    scan_phase1<<<sgrid, 128>>>();
    scan_phase3<<<sgrid, 128>>>(out);
}